// round 5
// baseline (speedup 1.0000x reference)
#include <cuda_runtime.h>
#include <cstdint>

#define Bc 32
#define Lc 4096
#define Hc 256
#define Nc 512
#define NROWS (Bc * Nc)          // 16384
#define TT 136
#define PROWS (Bc * TT)          // 4352
#define SLOPE 0.2f
#define NEGINF (-3.4028234663852886e38f)
#define EDGECAP (Nc * (Nc - 1) * 2)
#define WCAP 256

// copy partition: 8,388,608 float4 = 2048 blocks x 4096 float4
#define CPY_A 768
#define CPY_B 768
#define CPY_C 512

typedef unsigned long long u64;

// ---------------- scratch ----------------
__device__ __align__(16) float g_Y[(size_t)PROWS * 512];
__device__ __align__(16) float g_node[(size_t)NROWS * 256];
__device__ __align__(16) float g_agg[(size_t)NROWS * 256];
__device__ __align__(16) float g_add[(size_t)NROWS * 256];
__device__ float g_AT[NROWS];
__device__ float g_AS[NROWS];
__device__ float g_AE[2];
__device__ float g_E[2][256];
__device__ float g_w0[NROWS];
__device__ float g_w1[NROWS];
__device__ int   g_hn[NROWS];
__device__ int   g_bhas[Bc];
__device__ int   g_rowcnt[NROWS];
__device__ int   g_rowoff[NROWS];
__device__ int   g_cand[(size_t)Bc * EDGECAP];
__device__ int   g_rows[NROWS];
__device__ int   g_nact;
__device__ int   g_clist[(size_t)Bc * 128 * 512];
__device__ int   g_ccnt[Bc * 128];

// ---------------- f32x2 helpers ----------------
__device__ __forceinline__ u64 bcast2(float x) {
    u64 r; unsigned xi = __float_as_uint(x);
    asm("mov.b64 %0, {%1, %1};" : "=l"(r) : "r"(xi));
    return r;
}
__device__ __forceinline__ void ffma2(u64& d, u64 a, u64 b) {
    asm("fma.rn.f32x2 %0, %1, %2, %0;" : "+l"(d) : "l"(a), "l"(b));
}
__device__ __forceinline__ float2 unpk2(u64 v) {
    float2 r;
    asm("mov.b64 {%0, %1}, %2;" : "=f"(r.x), "=f"(r.y) : "l"(v));
    return r;
}

// ---------------- embedded copy block: 4096 float4 ----------------
__device__ __forceinline__ void copyBlk(float4* __restrict__ dst,
                                        const float4* __restrict__ src,
                                        int cblk, int tid)
{
    size_t base = ((size_t)cblk << 12) + tid;
#pragma unroll
    for (int i = 0; i < 16; i++) dst[base + (i << 8)] = src[base + (i << 8)];
}

// ============================================================================
// Shared GEMM tile body: 64x128 tile, k-step 16, col-pair f32x2 accumulators.
// Inputs: Aptr (thread's A row + k-group offset), Bptr (thread's B col base),
// outputs acc2[4][4] = rows trow..trow+3 x colpairs (tcol..tcol+7).
// ============================================================================
struct TileOut { u64 acc2[4][4]; };

__device__ __forceinline__ void gemmTile(
    const float* __restrict__ Aptr, const float* __restrict__ Bptr,
    float* As, float* Bs, int tid, TileOut& o)
{
    int aRow = tid >> 2, akg = (tid & 3) * 4;
    int bRowk = tid >> 4, bCol = (tid & 15) * 8;
    int trow = (tid >> 4) * 4, tcol = (tid & 15) * 8;

#pragma unroll
    for (int i = 0; i < 4; i++)
#pragma unroll
        for (int j = 0; j < 4; j++) o.acc2[i][j] = 0ull;

    float aR[4]; float bR[8];
    *(float4*)aR = *(const float4*)(Aptr);
    *(float4*)&bR[0] = *(const float4*)(Bptr);
    *(float4*)&bR[4] = *(const float4*)(Bptr + 4);

    for (int kt = 0; kt < 16; kt++) {
#pragma unroll
        for (int i = 0; i < 4; i++) As[(akg + i) * 68 + aRow] = aR[i];
        *(float4*)&Bs[bRowk * 128 + bCol]     = *(float4*)&bR[0];
        *(float4*)&Bs[bRowk * 128 + bCol + 4] = *(float4*)&bR[4];
        __syncthreads();
        if (kt < 15) {
            *(float4*)aR = *(const float4*)(Aptr + (kt + 1) * 16);
            const float* bp = Bptr + (size_t)((kt + 1) * 16) * 256;
            *(float4*)&bR[0] = *(const float4*)bp;
            *(float4*)&bR[4] = *(const float4*)(bp + 4);
        }
#pragma unroll
        for (int k = 0; k < 16; k++) {
            float a4[4];
            *(float4*)a4 = *(const float4*)&As[k * 68 + trow];
            u64 a2[4];
#pragma unroll
            for (int i = 0; i < 4; i++) a2[i] = bcast2(a4[i]);
            const u64* bp2 = (const u64*)&Bs[k * 128 + tcol];
            u64 b2[4];
#pragma unroll
            for (int j = 0; j < 4; j++) b2[j] = bp2[j];
#pragma unroll
            for (int i = 0; i < 4; i++)
#pragma unroll
                for (int j = 0; j < 4; j++) ffma2(o.acc2[i][j], a2[i], b2[j]);
        }
        __syncthreads();
    }
}

// ============================================================================
// L1: gemm0 (blocks 0..271: 64x128 tiles, grid 4x68) + build (272..303) + copyA
// ============================================================================
__global__ __launch_bounds__(256) void mega0Kernel(
    float* __restrict__ out, const float* __restrict__ emb,
    const float* __restrict__ W_trip,
    const int* __restrict__ asp_st, const int* __restrict__ asp_len,
    const int* __restrict__ opi_st, const int* __restrict__ opi_len,
    const float* __restrict__ edge_emb, const float* __restrict__ W_attn,
    const float* __restrict__ W_gat)
{
    int blk = blockIdx.x, tid = threadIdx.x;

    if (blk >= 304) {
        copyBlk((float4*)out, (const float4*)emb, blk - 304, tid);
        return;
    }

    if (blk < 272) {   // gemm0: Y[4352,512] = emb_tok @ Wcat
        __shared__ __align__(16) float As[16 * 68];
        __shared__ __align__(16) float Bs[16 * 128];
        int bc = blk & 3, br = blk >> 2;

        int aRow = tid >> 2, akg = (tid & 3) * 4;
        int r = br * 64 + aRow;
        int b = r / TT, t = r - b * TT;
        const float* Aptr = emb + ((size_t)(b * Lc + t)) * 256 + akg;

        int bRowk = tid >> 4, bCol = (tid & 15) * 8;
        int j = bc * 128 + bCol;
        int half = (j >= 256);
        const float* Bptr = W_trip + (size_t)(half * 256 + bRowk) * 256 + (j & 255);

        TileOut o;
        gemmTile(Aptr, Bptr, As, Bs, tid, o);

        int trow = (tid >> 4) * 4, tcol = (tid & 15) * 8;
#pragma unroll
        for (int i = 0; i < 4; i++) {
            int rr = br * 64 + trow + i;
#pragma unroll
            for (int jj = 0; jj < 4; jj++) {
                float2 v = unpk2(o.acc2[i][jj]);
                int c = bc * 128 + tcol + 2 * jj;
                *(float2*)&g_Y[(size_t)rr * 512 + c] = v;
            }
        }
        return;
    }

    // ---- build: per-batch CSR + center lists + misc scalars ----
    {
        int bb = blk - 272;
        int base = bb * Nc;
        __shared__ int ka[512], ko[512], cen[512];
        __shared__ int wsum[8];
        __shared__ int sc_cnt[128];
        for (int i = tid; i < 512; i += 256) {
            int st = asp_st[base + i], ln = asp_len[base + i];
            int so = opi_st[base + i], lo = opi_len[base + i];
            ka[i] = st | (ln << 16);
            ko[i] = so | (lo << 16);
            cen[i] = (st + so) >> 1;
        }
        if (tid < 128) sc_cnt[tid] = 0;
        __syncthreads();

        int t0 = 2 * tid, t1 = t0 + 1;
        int ka0 = ka[t0], ko0 = ko[t0], ce0 = cen[t0];
        int ka1 = ka[t1], ko1 = ko[t1], ce1 = cen[t1];
        int c0 = 0, c1 = 0, r0 = 0, r1 = 0;
        for (int s = 0; s < 512; s++) {
            int kas = ka[s], kos = ko[s], ces = cen[s];
            if (s != t0) c0 += (kas == ka0) + (kos == ko0);
            if (s != t1) c1 += (kas == ka1) + (kos == ko1);
            r0 += (s < t0 && ces == ce0);
            r1 += (s < t1 && ces == ce1);
        }
        int ps = c0 + c1;
        int lane = tid & 31, w = tid >> 5;
        int v = ps;
#pragma unroll
        for (int o = 1; o < 32; o <<= 1) {
            int n = __shfl_up_sync(0xffffffffu, v, o);
            if (lane >= o) v += n;
        }
        if (lane == 31) wsum[w] = v;
        __syncthreads();
        if (tid == 0) {
            int run = 0;
#pragma unroll
            for (int i = 0; i < 8; i++) { int x = wsum[i]; wsum[i] = run; run += x; }
        }
        __syncthreads();
        int off = v - ps + wsum[w];
        g_rowcnt[base + t0] = c0;
        g_rowcnt[base + t1] = c1;
        int p0 = bb * EDGECAP + off;
        int p1 = p0 + c0;
        g_rowoff[base + t0] = p0;
        g_rowoff[base + t1] = p1;
        for (int s = 0; s < 512; s++) {
            int kas = ka[s], kos = ko[s];
            if (s != t0) {
                if (kas == ka0) g_cand[p0++] = s;
                if (kos == ko0) g_cand[p0++] = s | (1 << 16);
            }
            if (s != t1) {
                if (kas == ka1) g_cand[p1++] = s;
                if (kos == ko1) g_cand[p1++] = s | (1 << 16);
            }
        }
        g_clist[((size_t)(bb * 128 + ce0) << 9) + r0] = t0;
        g_clist[((size_t)(bb * 128 + ce1) << 9) + r1] = t1;
        atomicAdd(&sc_cnt[ce0], 1);
        atomicAdd(&sc_cnt[ce1], 1);
        __syncthreads();
        if (tid < 128) g_ccnt[bb * 128 + tid] = sc_cnt[tid];

        if (bb == 0) {
            int h = tid;
#pragma unroll
            for (int e = 0; e < 2; e++) {
                float s = 0.f;
                for (int k = 0; k < 256; k++)
                    s += edge_emb[e * 256 + k] * W_gat[(size_t)(256 + k) * 256 + h];
                g_E[e][h] = s;
            }
            if (tid < 2) {
                float sa = 0.f;
                for (int k = 0; k < 256; k++) {
                    float vv = edge_emb[tid * 256 + k];
                    vv = (vv >= 0.f) ? vv : SLOPE * vv;
                    sa += vv * W_attn[512 + k];
                }
                g_AE[tid] = sa;
            }
            if (tid >= 4 && tid < 4 + Bc) g_bhas[tid - 4] = 0;
            if (tid == 2) g_nact = 0;
        }
    }
}

// ============================================================================
// L2: nodeStats (blocks 0..8191, 2 rows/block, float2) + copyB
// ============================================================================
__global__ __launch_bounds__(256) void nodeStatsKernel(
    float* __restrict__ out, const float* __restrict__ emb,
    const int* __restrict__ asp_st, const int* __restrict__ asp_len,
    const int* __restrict__ opi_st, const int* __restrict__ opi_len,
    const int* __restrict__ sent, const float* __restrict__ W_trip,
    const float* __restrict__ b_trip, const float* __restrict__ W_attn)
{
    int blk = blockIdx.x, tid = threadIdx.x;
    if (blk >= 8192) {
        copyBlk((float4*)out, (const float4*)emb, CPY_A + (blk - 8192), tid);
        return;
    }
    int half = tid >> 7;
    int hh = tid & 127;
    int row = blk * 2 + half;
    int b = row >> 9;
    const float2* Yb = (const float2*)(g_Y + (size_t)b * TT * 512);

    int ast = asp_st[row], aln = asp_len[row];
    int ost = opi_st[row], oln = opi_len[row];

    float2 asum = make_float2(0.f, 0.f);
#pragma unroll 4
    for (int k = 0; k <= aln; k++) {
        float2 v = Yb[(size_t)(ast + k) * 256 + hh];
        asum.x += v.x; asum.y += v.y;
    }
    float2 osum = make_float2(0.f, 0.f);
#pragma unroll 4
    for (int k = 0; k <= oln; k++) {
        float2 v = Yb[(size_t)(ost + k) * 256 + 128 + hh];
        osum.x += v.x; osum.y += v.y;
    }
    float ia = 1.f / (float)(aln + 1), io = 1.f / (float)(oln + 1);
    int sid = sent[row];
    float2 wt = ((const float2*)W_trip)[(size_t)(512 + sid) * 128 + hh];
    float2 bt = ((const float2*)b_trip)[hh];
    float2 v2;
    v2.x = asum.x * ia + osum.x * io + wt.x + bt.x;
    v2.y = asum.y * ia + osum.y * io + wt.y + bt.y;
    ((float2*)g_node)[((size_t)row << 7) + hh] = v2;

    float lx = (v2.x >= 0.f) ? v2.x : SLOPE * v2.x;
    float ly = (v2.y >= 0.f) ? v2.y : SLOPE * v2.y;
    float2 wa_t = ((const float2*)W_attn)[hh];
    float2 wa_s = ((const float2*)W_attn)[128 + hh];
    float at = lx * wa_t.x + ly * wa_t.y;
    float as = lx * wa_s.x + ly * wa_s.y;
#pragma unroll
    for (int o = 16; o; o >>= 1) {
        at += __shfl_xor_sync(0xffffffffu, at, o);
        as += __shfl_xor_sync(0xffffffffu, as, o);
    }
    __shared__ float sAt[8], sAs[8];
    int w = tid >> 5;
    if ((tid & 31) == 0) { sAt[w] = at; sAs[w] = as; }
    __syncthreads();
    if (hh == 0) {
        int w0 = half * 4;
        float a = sAt[w0] + sAt[w0 + 1] + sAt[w0 + 2] + sAt[w0 + 3];
        float s2 = sAs[w0] + sAs[w0 + 1] + sAs[w0 + 2] + sAs[w0 + 3];
        g_AT[row] = a;
        g_AS[row] = s2;
    }
}

// ============================================================================
// L3: edge (warp-per-row) + copyC
// ============================================================================
__global__ __launch_bounds__(256) void edgeKernel(
    float* __restrict__ out, const float* __restrict__ emb,
    const float* __restrict__ b_attn)
{
    int blk = blockIdx.x, tid = threadIdx.x;
    if (blk >= 2048) {
        copyBlk((float4*)out, (const float4*)emb, CPY_A + CPY_B + (blk - 2048), tid);
        return;
    }
    __shared__ int   s_cand[8][WCAP];
    __shared__ float s_sc[8][WCAP];
    int warp = tid >> 5, lane = tid & 31;
    int row = blk * 8 + warp;
    int b = row >> 9, bs = b * Nc;

    int m1 = g_rowcnt[row];
    if (m1 == 0) {
        if (lane == 0) g_hn[row] = 0;
        return;
    }
    if (m1 > WCAP) m1 = WCAP;
    int off = g_rowoff[row];
    for (int e = lane; e < m1; e += 32) s_cand[warp][e] = g_cand[off + e];

    const float* rp = g_node + ((size_t)row << 8);
    float nT[8];
#pragma unroll
    for (int k = 0; k < 8; k++) nT[k] = rp[lane + 32 * k];
    __syncwarp();

    float atv = g_AT[row], bat = b_attn[0];
    int m2 = 0;
    for (int e = 0; e < m1; e++) {
        int cd = s_cand[warp][e];
        int s = cd & 0xffff;
        const float* ns = g_node + ((size_t)(bs + s) << 8);
        float d = 0.f;
#pragma unroll
        for (int k = 0; k < 8; k++) d += nT[k] * ns[lane + 32 * k];
#pragma unroll
        for (int o = 16; o; o >>= 1) d += __shfl_xor_sync(0xffffffffu, d, o);
        if (lane == 0) {
            if (d > 0.f) { s_sc[warp][e] = atv + g_AS[bs + s] + g_AE[cd >> 16] + bat; m2++; }
            else s_sc[warp][e] = NEGINF;
        }
    }
    m2 = __shfl_sync(0xffffffffu, m2, 0);
    float invden = 0.f;
    if (lane == 0) {
        g_hn[row] = (m2 > 0) ? 1 : 0;
        if (m2 > 0) {
            atomicOr(&g_bhas[b], 1);
            int p = atomicAdd(&g_nact, 1);
            g_rows[p] = row;
            float mx = NEGINF;
            for (int e = 0; e < m1; e++) mx = fmaxf(mx, s_sc[warp][e]);
            float den = 0.f, w0 = 0.f, w1 = 0.f;
            for (int e = 0; e < m1; e++) {
                float we = expf(s_sc[warp][e] - mx);
                s_sc[warp][e] = we;
                den += we;
                if ((s_cand[warp][e] >> 16) == 0) w0 += we; else w1 += we;
            }
            invden = 1.f / den;
            g_w0[row] = w0 / den;
            g_w1[row] = w1 / den;
        }
    }
    invden = __shfl_sync(0xffffffffu, invden, 0);
    __syncwarp();
    if (m2 > 0) {
        float acc[8];
#pragma unroll
        for (int k = 0; k < 8; k++) acc[k] = 0.f;
        for (int e = 0; e < m1; e++) {
            float we = s_sc[warp][e];
            if (we != 0.f) {
                int s = s_cand[warp][e] & 0xffff;
                const float* ns = g_node + ((size_t)(bs + s) << 8);
#pragma unroll
                for (int k = 0; k < 8; k++) acc[k] += we * ns[lane + 32 * k];
            }
        }
        float* ag = g_agg + ((size_t)row << 8);
#pragma unroll
        for (int k = 0; k < 8; k++) ag[lane + 32 * k] = acc[k] * invden;
    }
}

// ============================================================================
// L4: GEMM1 on compacted active rows, 64x128 tiles, grid (2, 256)
// ============================================================================
__global__ __launch_bounds__(256) void gemm1Kernel(
    const float* __restrict__ W, const float* __restrict__ bias)
{
    int nact = g_nact;
    int bc = blockIdx.x, br = blockIdx.y;
    if (br * 64 >= nact) return;
    int nrows = nact - br * 64;
    if (nrows > 64) nrows = 64;

    __shared__ __align__(16) float As[16 * 68];
    __shared__ __align__(16) float Bs[16 * 128];
    __shared__ int rows[64];
    int tid = threadIdx.x;
    if (tid < 64) rows[tid] = g_rows[br * 64 + (tid < nrows ? tid : nrows - 1)];
    __syncthreads();

    int aRow = tid >> 2, akg = (tid & 3) * 4;
    const float* Aptr = g_agg + ((size_t)rows[aRow] << 8) + akg;
    int bRowk = tid >> 4, bCol = (tid & 15) * 8;
    const float* Bptr = W + (size_t)bRowk * 256 + bc * 128 + bCol;

    TileOut o;
    gemmTile(Aptr, Bptr, As, Bs, tid, o);

    int trow = (tid >> 4) * 4, tcol = (tid & 15) * 8;
#pragma unroll
    for (int i = 0; i < 4; i++) {
        int idx = trow + i;
        if (idx >= nrows) continue;
        int r = rows[idx];
        float w0 = g_w0[r], w1 = g_w1[r];
#pragma unroll
        for (int jj = 0; jj < 4; jj++) {
            float2 v = unpk2(o.acc2[i][jj]);
            int c = bc * 128 + tcol + 2 * jj;
            float ux = v.x + bias[c]     + w0 * g_E[0][c]     + w1 * g_E[1][c];
            float uy = v.y + bias[c + 1] + w0 * g_E[0][c + 1] + w1 * g_E[1][c + 1];
            float2 st;
            st.x = fmaxf(ux, 0.f);
            st.y = fmaxf(uy, 0.f);
            *(float2*)&g_add[((size_t)r << 8) + c] = st;
        }
    }
}

// ============================================================================
// L5: scatter via precomputed center lists
// ============================================================================
__global__ __launch_bounds__(256) void scatterKernel(float* __restrict__ out)
{
    int b = blockIdx.x >> 7;
    int c = blockIdx.x & 127;
    int h = threadIdx.x;
    if (!g_bhas[b]) return;
    int cnt = g_ccnt[b * 128 + c];
    if (cnt == 0) return;
    const int* list = g_clist + ((size_t)(b * 128 + c) << 9);
    float s = 0.f;
    for (int i = 0; i < cnt; i++) {
        int r = b * Nc + list[i];
        size_t o = ((size_t)r << 8) + h;
        s += g_hn[r] ? g_add[o] : g_node[o];
    }
    out[((size_t)b * Lc + c) * Hc + h] += s;
}

// ---------------- launch -----------------------------------------------------
extern "C" void kernel_launch(void* const* d_in, const int* in_sizes, int n_in,
                              void* d_out, int out_size)
{
    const float* emb     = (const float*)d_in[0];
    const float* W_trip  = (const float*)d_in[1];
    const float* b_trip  = (const float*)d_in[2];
    const float* edge_e  = (const float*)d_in[3];
    const float* W_attn  = (const float*)d_in[4];
    const float* b_attn  = (const float*)d_in[5];
    const float* W_gat   = (const float*)d_in[6];
    const float* b_gat   = (const float*)d_in[7];
    const int*   asp_st  = (const int*)d_in[8];
    const int*   asp_len = (const int*)d_in[9];
    const int*   opi_st  = (const int*)d_in[10];
    const int*   opi_len = (const int*)d_in[11];
    const int*   sent_id = (const int*)d_in[12];
    float* out = (float*)d_out;

    mega0Kernel<<<304 + CPY_A, 256>>>(out, emb, W_trip, asp_st, asp_len,
                                      opi_st, opi_len, edge_e, W_attn, W_gat);
    nodeStatsKernel<<<8192 + CPY_B, 256>>>(out, emb, asp_st, asp_len, opi_st, opi_len,
                                           sent_id, W_trip, b_trip, W_attn);
    edgeKernel<<<2048 + CPY_C, 256>>>(out, emb, b_attn);
    gemm1Kernel<<<dim3(2, 256), 256>>>(W_gat, b_gat);
    scatterKernel<<<Bc * 128, 256>>>(out);
}

// round 6
// speedup vs baseline: 1.1818x; 1.1818x over previous
#include <cuda_runtime.h>
#include <cstdint>

#define Bc 32
#define Lc 4096
#define Hc 256
#define Nc 512
#define NROWS (Bc * Nc)          // 16384
#define TT 136
#define PROWS (Bc * TT)          // 4352
#define SLOPE 0.2f
#define NEGINF (-3.4028234663852886e38f)
#define EDGECAP (Nc * (Nc - 1) * 2)
#define WCAP 256

// copy partition: 8,388,608 float4 = 2048 blocks x 4096 float4
#define CPY_A 768
#define CPY_B 768
#define CPY_C 512

typedef unsigned long long u64;
typedef unsigned int u32;

// ---------------- scratch ----------------
__device__ __align__(16) float g_Y[(size_t)PROWS * 512];
__device__ __align__(16) float g_node[(size_t)NROWS * 256];
__device__ __align__(16) float g_agg[(size_t)NROWS * 256];
__device__ __align__(16) float g_add[(size_t)NROWS * 256];
__device__ float g_AT[NROWS];
__device__ float g_AS[NROWS];
__device__ float g_AE[2];
__device__ float g_E[2][256];
__device__ float g_w0[NROWS];
__device__ float g_w1[NROWS];
__device__ int   g_hn[NROWS];
__device__ int   g_bhas[Bc];
__device__ int   g_rowcnt[NROWS];
__device__ int   g_rowoff[NROWS];
__device__ int   g_cand[(size_t)Bc * EDGECAP];
__device__ int   g_rows[NROWS];
__device__ int   g_nact;
__device__ int   g_clist[(size_t)Bc * 128 * 512];
__device__ int   g_ccnt[Bc * 128];

// ---------------- f32x2 helpers ----------------
__device__ __forceinline__ u64 bcast2(float x) {
    u64 r; unsigned xi = __float_as_uint(x);
    asm("mov.b64 %0, {%1, %1};" : "=l"(r) : "r"(xi));
    return r;
}
__device__ __forceinline__ void ffma2(u64& d, u64 a, u64 b) {
    asm("fma.rn.f32x2 %0, %1, %2, %0;" : "+l"(d) : "l"(a), "l"(b));
}
__device__ __forceinline__ float2 unpk2(u64 v) {
    float2 r;
    asm("mov.b64 {%0, %1}, %2;" : "=f"(r.x), "=f"(r.y) : "l"(v));
    return r;
}
__device__ __forceinline__ u32 f2tf32(float f) {
    u32 r;
    asm("cvt.rna.tf32.f32 %0, %1;" : "=r"(r) : "f"(f));
    return r;
}

// ---------------- embedded copy block: 4096 float4 ----------------
__device__ __forceinline__ void copyBlk(float4* __restrict__ dst,
                                        const float4* __restrict__ src,
                                        int cblk, int tid)
{
    size_t base = ((size_t)cblk << 12) + tid;
#pragma unroll
    for (int i = 0; i < 16; i++) dst[base + (i << 8)] = src[base + (i << 8)];
}

// ============================================================================
// L1: gemm0 (blocks 0..135, 128x128 FFMA2) + build (136..167) + copyA
// ============================================================================
__global__ __launch_bounds__(256) void mega0Kernel(
    float* __restrict__ out, const float* __restrict__ emb,
    const float* __restrict__ W_trip,
    const int* __restrict__ asp_st, const int* __restrict__ asp_len,
    const int* __restrict__ opi_st, const int* __restrict__ opi_len,
    const float* __restrict__ edge_emb, const float* __restrict__ W_attn,
    const float* __restrict__ W_gat)
{
    int blk = blockIdx.x, tid = threadIdx.x;

    if (blk >= 168) {
        copyBlk((float4*)out, (const float4*)emb, blk - 168, tid);
        return;
    }

    if (blk < 136) {    // gemm0: Y = emb_tok[4352,256] @ Wcat[256,512]
        __shared__ __align__(16) float As[8][128];
        __shared__ __align__(16) float Bs[8][128];
        int bc = blk & 3, br = blk >> 2;
        int aRow = tid >> 1, aCol = (tid & 1) * 4;
        int bRow = tid >> 5, bCol = (tid & 31) * 4;

        int r = br * 128 + aRow;
        int b = r / TT;
        int t = r - b * TT;
        const float* Aptr = emb + ((size_t)(b * Lc + t)) * 256 + aCol;
        int j = bc * 128 + bCol;
        int half = (j >= 256);
        const float* Bptr = W_trip + (size_t)(half * 256 + bRow) * 256 + (j & 255);

        u64 acc2[4][8];
#pragma unroll
        for (int i = 0; i < 4; i++)
#pragma unroll
            for (int jj = 0; jj < 8; jj++) acc2[i][jj] = 0ull;

        int trow = (tid >> 4) * 8;
        int tcol = (tid & 15) * 8;

        for (int k0 = 0; k0 < 256; k0 += 8) {
            float4 av = *(const float4*)(Aptr + k0);
            As[aCol + 0][aRow] = av.x;
            As[aCol + 1][aRow] = av.y;
            As[aCol + 2][aRow] = av.z;
            As[aCol + 3][aRow] = av.w;
            float4 bv = *(const float4*)(Bptr + (size_t)k0 * 256);
            *(float4*)&Bs[bRow][bCol] = bv;
            __syncthreads();
#pragma unroll
            for (int k = 0; k < 8; k++) {
                const u64* a64 = (const u64*)&As[k][trow];
                u64 a2[4] = { a64[0], a64[1], a64[2], a64[3] };
                float bb[8];
                *(float4*)&bb[0] = *(const float4*)&Bs[k][tcol];
                *(float4*)&bb[4] = *(const float4*)&Bs[k][tcol + 4];
                u64 b2[8];
#pragma unroll
                for (int jj = 0; jj < 8; jj++) b2[jj] = bcast2(bb[jj]);
#pragma unroll
                for (int i = 0; i < 4; i++)
#pragma unroll
                    for (int jj = 0; jj < 8; jj++) ffma2(acc2[i][jj], a2[i], b2[jj]);
            }
            __syncthreads();
        }
#pragma unroll
        for (int i2 = 0; i2 < 4; i2++) {
            int r0 = br * 128 + trow + 2 * i2;
#pragma unroll
            for (int jj = 0; jj < 8; jj++) {
                float2 v = unpk2(acc2[i2][jj]);
                int c = bc * 128 + tcol + jj;
                g_Y[(size_t)r0 * 512 + c]       = v.x;
                g_Y[(size_t)(r0 + 1) * 512 + c] = v.y;
            }
        }
        return;
    }

    // ---- build: per-batch CSR + center lists + misc scalars ----
    {
        int bb = blk - 136;
        int base = bb * Nc;
        __shared__ int ka[512], ko[512], cen[512];
        __shared__ int wsum[8];
        __shared__ int sc_cnt[128];
        for (int i = tid; i < 512; i += 256) {
            int st = asp_st[base + i], ln = asp_len[base + i];
            int so = opi_st[base + i], lo = opi_len[base + i];
            ka[i] = st | (ln << 16);
            ko[i] = so | (lo << 16);
            cen[i] = (st + so) >> 1;
        }
        if (tid < 128) sc_cnt[tid] = 0;
        __syncthreads();

        int t0 = 2 * tid, t1 = t0 + 1;
        int ka0 = ka[t0], ko0 = ko[t0], ce0 = cen[t0];
        int ka1 = ka[t1], ko1 = ko[t1], ce1 = cen[t1];
        int c0 = 0, c1 = 0, r0 = 0, r1 = 0;
        for (int s = 0; s < 512; s++) {
            int kas = ka[s], kos = ko[s], ces = cen[s];
            if (s != t0) c0 += (kas == ka0) + (kos == ko0);
            if (s != t1) c1 += (kas == ka1) + (kos == ko1);
            r0 += (s < t0 && ces == ce0);
            r1 += (s < t1 && ces == ce1);
        }
        int ps = c0 + c1;
        int lane = tid & 31, w = tid >> 5;
        int v = ps;
#pragma unroll
        for (int o = 1; o < 32; o <<= 1) {
            int n = __shfl_up_sync(0xffffffffu, v, o);
            if (lane >= o) v += n;
        }
        if (lane == 31) wsum[w] = v;
        __syncthreads();
        if (tid == 0) {
            int run = 0;
#pragma unroll
            for (int i = 0; i < 8; i++) { int x = wsum[i]; wsum[i] = run; run += x; }
        }
        __syncthreads();
        int off = v - ps + wsum[w];
        g_rowcnt[base + t0] = c0;
        g_rowcnt[base + t1] = c1;
        int p0 = bb * EDGECAP + off;
        int p1 = p0 + c0;
        g_rowoff[base + t0] = p0;
        g_rowoff[base + t1] = p1;
        for (int s = 0; s < 512; s++) {
            int kas = ka[s], kos = ko[s];
            if (s != t0) {
                if (kas == ka0) g_cand[p0++] = s;
                if (kos == ko0) g_cand[p0++] = s | (1 << 16);
            }
            if (s != t1) {
                if (kas == ka1) g_cand[p1++] = s;
                if (kos == ko1) g_cand[p1++] = s | (1 << 16);
            }
        }
        g_clist[((size_t)(bb * 128 + ce0) << 9) + r0] = t0;
        g_clist[((size_t)(bb * 128 + ce1) << 9) + r1] = t1;
        atomicAdd(&sc_cnt[ce0], 1);
        atomicAdd(&sc_cnt[ce1], 1);
        __syncthreads();
        if (tid < 128) g_ccnt[bb * 128 + tid] = sc_cnt[tid];

        if (bb == 0) {
            int h = tid;
#pragma unroll
            for (int e = 0; e < 2; e++) {
                float s = 0.f;
                for (int k = 0; k < 256; k++)
                    s += edge_emb[e * 256 + k] * W_gat[(size_t)(256 + k) * 256 + h];
                g_E[e][h] = s;
            }
            if (tid < 2) {
                float sa = 0.f;
                for (int k = 0; k < 256; k++) {
                    float vv = edge_emb[tid * 256 + k];
                    vv = (vv >= 0.f) ? vv : SLOPE * vv;
                    sa += vv * W_attn[512 + k];
                }
                g_AE[tid] = sa;
            }
            if (tid >= 4 && tid < 4 + Bc) g_bhas[tid - 4] = 0;
            if (tid == 2) g_nact = 0;
        }
    }
}

// ============================================================================
// L2: nodeStats (blocks 0..8191, 2 rows/block, float2) + copyB
// ============================================================================
__global__ __launch_bounds__(256) void nodeStatsKernel(
    float* __restrict__ out, const float* __restrict__ emb,
    const int* __restrict__ asp_st, const int* __restrict__ asp_len,
    const int* __restrict__ opi_st, const int* __restrict__ opi_len,
    const int* __restrict__ sent, const float* __restrict__ W_trip,
    const float* __restrict__ b_trip, const float* __restrict__ W_attn)
{
    int blk = blockIdx.x, tid = threadIdx.x;
    if (blk >= 8192) {
        copyBlk((float4*)out, (const float4*)emb, CPY_A + (blk - 8192), tid);
        return;
    }
    int half = tid >> 7;
    int hh = tid & 127;
    int row = blk * 2 + half;
    int b = row >> 9;
    const float2* Yb = (const float2*)(g_Y + (size_t)b * TT * 512);

    int ast = asp_st[row], aln = asp_len[row];
    int ost = opi_st[row], oln = opi_len[row];

    float2 asum = make_float2(0.f, 0.f);
#pragma unroll 4
    for (int k = 0; k <= aln; k++) {
        float2 v = Yb[(size_t)(ast + k) * 256 + hh];
        asum.x += v.x; asum.y += v.y;
    }
    float2 osum = make_float2(0.f, 0.f);
#pragma unroll 4
    for (int k = 0; k <= oln; k++) {
        float2 v = Yb[(size_t)(ost + k) * 256 + 128 + hh];
        osum.x += v.x; osum.y += v.y;
    }
    float ia = 1.f / (float)(aln + 1), io = 1.f / (float)(oln + 1);
    int sid = sent[row];
    float2 wt = ((const float2*)W_trip)[(size_t)(512 + sid) * 128 + hh];
    float2 bt = ((const float2*)b_trip)[hh];
    float2 v2;
    v2.x = asum.x * ia + osum.x * io + wt.x + bt.x;
    v2.y = asum.y * ia + osum.y * io + wt.y + bt.y;
    ((float2*)g_node)[((size_t)row << 7) + hh] = v2;

    float lx = (v2.x >= 0.f) ? v2.x : SLOPE * v2.x;
    float ly = (v2.y >= 0.f) ? v2.y : SLOPE * v2.y;
    float2 wa_t = ((const float2*)W_attn)[hh];
    float2 wa_s = ((const float2*)W_attn)[128 + hh];
    float at = lx * wa_t.x + ly * wa_t.y;
    float as = lx * wa_s.x + ly * wa_s.y;
#pragma unroll
    for (int o = 16; o; o >>= 1) {
        at += __shfl_xor_sync(0xffffffffu, at, o);
        as += __shfl_xor_sync(0xffffffffu, as, o);
    }
    __shared__ float sAt[8], sAs[8];
    int w = tid >> 5;
    if ((tid & 31) == 0) { sAt[w] = at; sAs[w] = as; }
    __syncthreads();
    if (hh == 0) {
        int w0 = half * 4;
        float a = sAt[w0] + sAt[w0 + 1] + sAt[w0 + 2] + sAt[w0 + 3];
        float s2 = sAs[w0] + sAs[w0 + 1] + sAs[w0 + 2] + sAs[w0 + 3];
        g_AT[row] = a;
        g_AS[row] = s2;
    }
}

// ============================================================================
// L3: edge (warp-per-row) + copyC
// ============================================================================
__global__ __launch_bounds__(256) void edgeKernel(
    float* __restrict__ out, const float* __restrict__ emb,
    const float* __restrict__ b_attn)
{
    int blk = blockIdx.x, tid = threadIdx.x;
    if (blk >= 2048) {
        copyBlk((float4*)out, (const float4*)emb, CPY_A + CPY_B + (blk - 2048), tid);
        return;
    }
    __shared__ int   s_cand[8][WCAP];
    __shared__ float s_sc[8][WCAP];
    int warp = tid >> 5, lane = tid & 31;
    int row = blk * 8 + warp;
    int b = row >> 9, bs = b * Nc;

    int m1 = g_rowcnt[row];
    if (m1 == 0) {
        if (lane == 0) g_hn[row] = 0;
        return;
    }
    if (m1 > WCAP) m1 = WCAP;
    int off = g_rowoff[row];
    for (int e = lane; e < m1; e += 32) s_cand[warp][e] = g_cand[off + e];

    const float* rp = g_node + ((size_t)row << 8);
    float nT[8];
#pragma unroll
    for (int k = 0; k < 8; k++) nT[k] = rp[lane + 32 * k];
    __syncwarp();

    float atv = g_AT[row], bat = b_attn[0];
    int m2 = 0;
    for (int e = 0; e < m1; e++) {
        int cd = s_cand[warp][e];
        int s = cd & 0xffff;
        const float* ns = g_node + ((size_t)(bs + s) << 8);
        float d = 0.f;
#pragma unroll
        for (int k = 0; k < 8; k++) d += nT[k] * ns[lane + 32 * k];
#pragma unroll
        for (int o = 16; o; o >>= 1) d += __shfl_xor_sync(0xffffffffu, d, o);
        if (lane == 0) {
            if (d > 0.f) { s_sc[warp][e] = atv + g_AS[bs + s] + g_AE[cd >> 16] + bat; m2++; }
            else s_sc[warp][e] = NEGINF;
        }
    }
    m2 = __shfl_sync(0xffffffffu, m2, 0);
    float invden = 0.f;
    if (lane == 0) {
        g_hn[row] = (m2 > 0) ? 1 : 0;
        if (m2 > 0) {
            atomicOr(&g_bhas[b], 1);
            int p = atomicAdd(&g_nact, 1);
            g_rows[p] = row;
            float mx = NEGINF;
            for (int e = 0; e < m1; e++) mx = fmaxf(mx, s_sc[warp][e]);
            float den = 0.f, w0 = 0.f, w1 = 0.f;
            for (int e = 0; e < m1; e++) {
                float we = expf(s_sc[warp][e] - mx);
                s_sc[warp][e] = we;
                den += we;
                if ((s_cand[warp][e] >> 16) == 0) w0 += we; else w1 += we;
            }
            invden = 1.f / den;
            g_w0[row] = w0 / den;
            g_w1[row] = w1 / den;
        }
    }
    invden = __shfl_sync(0xffffffffu, invden, 0);
    __syncwarp();
    if (m2 > 0) {
        float acc[8];
#pragma unroll
        for (int k = 0; k < 8; k++) acc[k] = 0.f;
        for (int e = 0; e < m1; e++) {
            float we = s_sc[warp][e];
            if (we != 0.f) {
                int s = s_cand[warp][e] & 0xffff;
                const float* ns = g_node + ((size_t)(bs + s) << 8);
#pragma unroll
                for (int k = 0; k < 8; k++) acc[k] += we * ns[lane + 32 * k];
            }
        }
        float* ag = g_agg + ((size_t)row << 8);
#pragma unroll
        for (int k = 0; k < 8; k++) ag[lane + 32 * k] = acc[k] * invden;
    }
}

// ============================================================================
// L4: GEMM1 via tf32 mma.sync.m16n8k8 — 64 rows x 256 cols per block
// ============================================================================
#define AS_STRIDE 20
#define BS_STRIDE 264

__global__ __launch_bounds__(256) void gemm1Kernel(
    const float* __restrict__ W, const float* __restrict__ bias)
{
    int nact = g_nact;
    int br = blockIdx.x;
    if (br * 64 >= nact) return;
    int nrows = nact - br * 64;
    if (nrows > 64) nrows = 64;

    __shared__ __align__(16) u32 As[64 * AS_STRIDE];   // tf32 bits, 64 rows x 16 k
    __shared__ __align__(16) u32 Bs[16 * BS_STRIDE];   // tf32 bits, 16 k x 256 n
    __shared__ float sB[256], sE0[256], sE1[256];
    __shared__ int rows[64];

    int tid = threadIdx.x;
    int lane = tid & 31, wid = tid >> 5;
    int wm = wid & 3, wn = wid >> 2;   // warp tile: rows wm*16.., cols wn*128..

    if (tid < 64) rows[tid] = g_rows[br * 64 + (tid < nrows ? tid : nrows - 1)];
    sB[tid]  = bias[tid];
    sE0[tid] = g_E[0][tid];
    sE1[tid] = g_E[1][tid];
    __syncthreads();

    // A gather: thread loads row rows[tid>>2], float4 at col (tid&3)*4 per chunk
    const float* Ap = g_agg + ((size_t)rows[tid >> 2] << 8) + (tid & 3) * 4;
    u32* AsW = &As[(tid >> 2) * AS_STRIDE + (tid & 3) * 4];
    // B: thread loads k-row (tid>>4), 4 float4 at cols (tid&15)*16 + l*4
    int bkr = tid >> 4, bcg = (tid & 15) * 16;
    const float* Bp = W + (size_t)bkr * 256 + bcg;
    u32* BsW = &Bs[bkr * BS_STRIDE + bcg];

    float C[16][4];
#pragma unroll
    for (int j = 0; j < 16; j++)
#pragma unroll
        for (int i = 0; i < 4; i++) C[j][i] = 0.f;

    int g = lane >> 2, cc = lane & 3;

    for (int kc = 0; kc < 16; kc++) {
        float4 av = *(const float4*)(Ap + kc * 16);
        AsW[0] = f2tf32(av.x); AsW[1] = f2tf32(av.y);
        AsW[2] = f2tf32(av.z); AsW[3] = f2tf32(av.w);
#pragma unroll
        for (int l = 0; l < 4; l++) {
            float4 bv = *(const float4*)(Bp + (size_t)(kc * 16) * 256 + l * 4);
            BsW[l * 4 + 0] = f2tf32(bv.x); BsW[l * 4 + 1] = f2tf32(bv.y);
            BsW[l * 4 + 2] = f2tf32(bv.z); BsW[l * 4 + 3] = f2tf32(bv.w);
        }
        __syncthreads();
#pragma unroll
        for (int ks = 0; ks < 16; ks += 8) {
            u32 a0 = As[(wm * 16 + g)     * AS_STRIDE + ks + cc];
            u32 a1 = As[(wm * 16 + g + 8) * AS_STRIDE + ks + cc];
            u32 a2 = As[(wm * 16 + g)     * AS_STRIDE + ks + cc + 4];
            u32 a3 = As[(wm * 16 + g + 8) * AS_STRIDE + ks + cc + 4];
            const u32* b0p = &Bs[(ks + cc)     * BS_STRIDE + wn * 128 + g];
            const u32* b1p = &Bs[(ks + cc + 4) * BS_STRIDE + wn * 128 + g];
#pragma unroll
            for (int j = 0; j < 16; j++) {
                u32 b0 = b0p[j * 8];
                u32 b1 = b1p[j * 8];
                asm volatile(
                    "mma.sync.aligned.m16n8k8.row.col.f32.tf32.tf32.f32 "
                    "{%0,%1,%2,%3}, {%4,%5,%6,%7}, {%8,%9}, {%0,%1,%2,%3};"
                    : "+f"(C[j][0]), "+f"(C[j][1]), "+f"(C[j][2]), "+f"(C[j][3])
                    : "r"(a0), "r"(a1), "r"(a2), "r"(a3), "r"(b0), "r"(b1));
            }
        }
        __syncthreads();
    }

    // epilogue: two rows per thread (g, g+8)
    int idx0 = wm * 16 + g, idx1 = idx0 + 8;
    bool ok0 = idx0 < nrows, ok1 = idx1 < nrows;
    int r0 = rows[idx0], r1 = rows[idx1];
    float w00 = g_w0[r0], w01 = g_w1[r0];
    float w10 = g_w0[r1], w11 = g_w1[r1];
#pragma unroll
    for (int j = 0; j < 16; j++) {
        int col = wn * 128 + j * 8 + 2 * cc;
        float bx = sB[col],     e0x = sE0[col],     e1x = sE1[col];
        float by = sB[col + 1], e0y = sE0[col + 1], e1y = sE1[col + 1];
        if (ok0) {
            float2 st;
            st.x = fmaxf(C[j][0] + bx + w00 * e0x + w01 * e1x, 0.f);
            st.y = fmaxf(C[j][1] + by + w00 * e0y + w01 * e1y, 0.f);
            *(float2*)&g_add[((size_t)r0 << 8) + col] = st;
        }
        if (ok1) {
            float2 st;
            st.x = fmaxf(C[j][2] + bx + w10 * e0x + w11 * e1x, 0.f);
            st.y = fmaxf(C[j][3] + by + w10 * e0y + w11 * e1y, 0.f);
            *(float2*)&g_add[((size_t)r1 << 8) + col] = st;
        }
    }
}

// ============================================================================
// L5: scatter via precomputed center lists
// ============================================================================
__global__ __launch_bounds__(256) void scatterKernel(float* __restrict__ out)
{
    int b = blockIdx.x >> 7;
    int c = blockIdx.x & 127;
    int h = threadIdx.x;
    if (!g_bhas[b]) return;
    int cnt = g_ccnt[b * 128 + c];
    if (cnt == 0) return;
    const int* list = g_clist + ((size_t)(b * 128 + c) << 9);
    float s = 0.f;
    for (int i = 0; i < cnt; i++) {
        int r = b * Nc + list[i];
        size_t o = ((size_t)r << 8) + h;
        s += g_hn[r] ? g_add[o] : g_node[o];
    }
    out[((size_t)b * Lc + c) * Hc + h] += s;
}

// ---------------- launch -----------------------------------------------------
extern "C" void kernel_launch(void* const* d_in, const int* in_sizes, int n_in,
                              void* d_out, int out_size)
{
    const float* emb     = (const float*)d_in[0];
    const float* W_trip  = (const float*)d_in[1];
    const float* b_trip  = (const float*)d_in[2];
    const float* edge_e  = (const float*)d_in[3];
    const float* W_attn  = (const float*)d_in[4];
    const float* b_attn  = (const float*)d_in[5];
    const float* W_gat   = (const float*)d_in[6];
    const float* b_gat   = (const float*)d_in[7];
    const int*   asp_st  = (const int*)d_in[8];
    const int*   asp_len = (const int*)d_in[9];
    const int*   opi_st  = (const int*)d_in[10];
    const int*   opi_len = (const int*)d_in[11];
    const int*   sent_id = (const int*)d_in[12];
    float* out = (float*)d_out;

    mega0Kernel<<<168 + CPY_A, 256>>>(out, emb, W_trip, asp_st, asp_len,
                                      opi_st, opi_len, edge_e, W_attn, W_gat);
    nodeStatsKernel<<<8192 + CPY_B, 256>>>(out, emb, asp_st, asp_len, opi_st, opi_len,
                                           sent_id, W_trip, b_trip, W_attn);
    edgeKernel<<<2048 + CPY_C, 256>>>(out, emb, b_attn);
    gemm1Kernel<<<256, 256>>>(W_gat, b_gat);
    scatterKernel<<<Bc * 128, 256>>>(out);
}

// round 7
// speedup vs baseline: 1.1940x; 1.0103x over previous
#include <cuda_runtime.h>
#include <cstdint>

#define Bc 32
#define Lc 4096
#define Hc 256
#define Nc 512
#define NROWS (Bc * Nc)          // 16384
#define TT 136
#define PROWS (Bc * TT)          // 4352
#define SLOPE 0.2f
#define NEGINF (-3.4028234663852886e38f)
#define EDGECAP (Nc * (Nc - 1) * 2)
#define WCAP 256

// copy partition: 8,388,608 float4 = 2048 blocks x 4096 float4
#define CPY_A 768
#define CPY_B 768
#define CPY_C 512

typedef unsigned long long u64;
typedef unsigned int u32;

// ---------------- scratch ----------------
__device__ __align__(16) float g_Y[(size_t)PROWS * 512];
__device__ __align__(16) float g_node[(size_t)NROWS * 256];
__device__ __align__(16) float g_agg[(size_t)NROWS * 256];
__device__ __align__(16) float g_add[(size_t)NROWS * 256];
__device__ float g_AT[NROWS];
__device__ float g_AS[NROWS];
__device__ float g_AE[2];
__device__ float g_E[2][256];
__device__ float g_w0[NROWS];
__device__ float g_w1[NROWS];
__device__ int   g_hn[NROWS];
__device__ int   g_bhas[Bc];
__device__ int   g_rowcnt[NROWS];
__device__ int   g_rowoff[NROWS];
__device__ int   g_cand[(size_t)Bc * EDGECAP];
__device__ int   g_rows[NROWS];
__device__ int   g_nact;
__device__ int   g_clist[(size_t)Bc * 128 * 512];
__device__ int   g_ccnt[Bc * 128];

// ---------------- f32x2 helpers ----------------
__device__ __forceinline__ u64 bcast2(float x) {
    u64 r; unsigned xi = __float_as_uint(x);
    asm("mov.b64 %0, {%1, %1};" : "=l"(r) : "r"(xi));
    return r;
}
__device__ __forceinline__ void ffma2(u64& d, u64 a, u64 b) {
    asm("fma.rn.f32x2 %0, %1, %2, %0;" : "+l"(d) : "l"(a), "l"(b));
}
__device__ __forceinline__ float2 unpk2(u64 v) {
    float2 r;
    asm("mov.b64 {%0, %1}, %2;" : "=f"(r.x), "=f"(r.y) : "l"(v));
    return r;
}
__device__ __forceinline__ u32 f2tf32(float f) {
    u32 r;
    asm("cvt.rna.tf32.f32 %0, %1;" : "=r"(r) : "f"(f));
    return r;
}

// ---------------- embedded copy block: 4096 float4 ----------------
__device__ __forceinline__ void copyBlk(float4* __restrict__ dst,
                                        const float4* __restrict__ src,
                                        int cblk, int tid)
{
    size_t base = ((size_t)cblk << 12) + tid;
#pragma unroll
    for (int i = 0; i < 16; i++) dst[base + (i << 8)] = src[base + (i << 8)];
}

// ============================================================================
// L1: gemm0 (blocks 0..135, 128x128 FFMA2) + build (136..167) + copyA
// ============================================================================
__global__ __launch_bounds__(256) void mega0Kernel(
    float* __restrict__ out, const float* __restrict__ emb,
    const float* __restrict__ W_trip,
    const int* __restrict__ asp_st, const int* __restrict__ asp_len,
    const int* __restrict__ opi_st, const int* __restrict__ opi_len,
    const float* __restrict__ edge_emb, const float* __restrict__ W_attn,
    const float* __restrict__ W_gat)
{
    int blk = blockIdx.x, tid = threadIdx.x;

    if (blk >= 168) {
        copyBlk((float4*)out, (const float4*)emb, blk - 168, tid);
        return;
    }

    if (blk < 136) {    // gemm0: Y = emb_tok[4352,256] @ Wcat[256,512]
        __shared__ __align__(16) float As[8][128];
        __shared__ __align__(16) float Bs[8][128];
        int bc = blk & 3, br = blk >> 2;
        int aRow = tid >> 1, aCol = (tid & 1) * 4;
        int bRow = tid >> 5, bCol = (tid & 31) * 4;

        int r = br * 128 + aRow;
        int b = r / TT;
        int t = r - b * TT;
        const float* Aptr = emb + ((size_t)(b * Lc + t)) * 256 + aCol;
        int j = bc * 128 + bCol;
        int half = (j >= 256);
        const float* Bptr = W_trip + (size_t)(half * 256 + bRow) * 256 + (j & 255);

        u64 acc2[4][8];
#pragma unroll
        for (int i = 0; i < 4; i++)
#pragma unroll
            for (int jj = 0; jj < 8; jj++) acc2[i][jj] = 0ull;

        int trow = (tid >> 4) * 8;
        int tcol = (tid & 15) * 8;

        for (int k0 = 0; k0 < 256; k0 += 8) {
            float4 av = *(const float4*)(Aptr + k0);
            As[aCol + 0][aRow] = av.x;
            As[aCol + 1][aRow] = av.y;
            As[aCol + 2][aRow] = av.z;
            As[aCol + 3][aRow] = av.w;
            float4 bv = *(const float4*)(Bptr + (size_t)k0 * 256);
            *(float4*)&Bs[bRow][bCol] = bv;
            __syncthreads();
#pragma unroll
            for (int k = 0; k < 8; k++) {
                const u64* a64 = (const u64*)&As[k][trow];
                u64 a2[4] = { a64[0], a64[1], a64[2], a64[3] };
                float bb[8];
                *(float4*)&bb[0] = *(const float4*)&Bs[k][tcol];
                *(float4*)&bb[4] = *(const float4*)&Bs[k][tcol + 4];
                u64 b2[8];
#pragma unroll
                for (int jj = 0; jj < 8; jj++) b2[jj] = bcast2(bb[jj]);
#pragma unroll
                for (int i = 0; i < 4; i++)
#pragma unroll
                    for (int jj = 0; jj < 8; jj++) ffma2(acc2[i][jj], a2[i], b2[jj]);
            }
            __syncthreads();
        }
#pragma unroll
        for (int i2 = 0; i2 < 4; i2++) {
            int r0 = br * 128 + trow + 2 * i2;
#pragma unroll
            for (int jj = 0; jj < 8; jj++) {
                float2 v = unpk2(acc2[i2][jj]);
                int c = bc * 128 + tcol + jj;
                g_Y[(size_t)r0 * 512 + c]       = v.x;
                g_Y[(size_t)(r0 + 1) * 512 + c] = v.y;
            }
        }
        return;
    }

    // ---- build: per-batch CSR + center lists + misc scalars ----
    {
        int bb = blk - 136;
        int base = bb * Nc;
        __shared__ int ka[512], ko[512], cen[512];
        __shared__ int wsum[8];
        __shared__ int sc_cnt[128];
        for (int i = tid; i < 512; i += 256) {
            int st = asp_st[base + i], ln = asp_len[base + i];
            int so = opi_st[base + i], lo = opi_len[base + i];
            ka[i] = st | (ln << 16);
            ko[i] = so | (lo << 16);
            cen[i] = (st + so) >> 1;
        }
        if (tid < 128) sc_cnt[tid] = 0;
        __syncthreads();

        int t0 = 2 * tid, t1 = t0 + 1;
        int ka0 = ka[t0], ko0 = ko[t0], ce0 = cen[t0];
        int ka1 = ka[t1], ko1 = ko[t1], ce1 = cen[t1];
        int c0 = 0, c1 = 0, r0 = 0, r1 = 0;
        for (int s = 0; s < 512; s++) {
            int kas = ka[s], kos = ko[s], ces = cen[s];
            if (s != t0) c0 += (kas == ka0) + (kos == ko0);
            if (s != t1) c1 += (kas == ka1) + (kos == ko1);
            r0 += (s < t0 && ces == ce0);
            r1 += (s < t1 && ces == ce1);
        }
        int ps = c0 + c1;
        int lane = tid & 31, w = tid >> 5;
        int v = ps;
#pragma unroll
        for (int o = 1; o < 32; o <<= 1) {
            int n = __shfl_up_sync(0xffffffffu, v, o);
            if (lane >= o) v += n;
        }
        if (lane == 31) wsum[w] = v;
        __syncthreads();
        if (tid == 0) {
            int run = 0;
#pragma unroll
            for (int i = 0; i < 8; i++) { int x = wsum[i]; wsum[i] = run; run += x; }
        }
        __syncthreads();
        int off = v - ps + wsum[w];
        g_rowcnt[base + t0] = c0;
        g_rowcnt[base + t1] = c1;
        int p0 = bb * EDGECAP + off;
        int p1 = p0 + c0;
        g_rowoff[base + t0] = p0;
        g_rowoff[base + t1] = p1;
        for (int s = 0; s < 512; s++) {
            int kas = ka[s], kos = ko[s];
            if (s != t0) {
                if (kas == ka0) g_cand[p0++] = s;
                if (kos == ko0) g_cand[p0++] = s | (1 << 16);
            }
            if (s != t1) {
                if (kas == ka1) g_cand[p1++] = s;
                if (kos == ko1) g_cand[p1++] = s | (1 << 16);
            }
        }
        g_clist[((size_t)(bb * 128 + ce0) << 9) + r0] = t0;
        g_clist[((size_t)(bb * 128 + ce1) << 9) + r1] = t1;
        atomicAdd(&sc_cnt[ce0], 1);
        atomicAdd(&sc_cnt[ce1], 1);
        __syncthreads();
        if (tid < 128) g_ccnt[bb * 128 + tid] = sc_cnt[tid];

        if (bb == 0) {
            int h = tid;
#pragma unroll
            for (int e = 0; e < 2; e++) {
                float s = 0.f;
                for (int k = 0; k < 256; k++)
                    s += edge_emb[e * 256 + k] * W_gat[(size_t)(256 + k) * 256 + h];
                g_E[e][h] = s;
            }
            if (tid < 2) {
                float sa = 0.f;
                for (int k = 0; k < 256; k++) {
                    float vv = edge_emb[tid * 256 + k];
                    vv = (vv >= 0.f) ? vv : SLOPE * vv;
                    sa += vv * W_attn[512 + k];
                }
                g_AE[tid] = sa;
            }
            if (tid >= 4 && tid < 4 + Bc) g_bhas[tid - 4] = 0;
            if (tid == 2) g_nact = 0;
        }
    }
}

// ============================================================================
// L2: nodeStats (blocks 0..8191, 2 rows/block, float2) + copyB
// ============================================================================
__global__ __launch_bounds__(256) void nodeStatsKernel(
    float* __restrict__ out, const float* __restrict__ emb,
    const int* __restrict__ asp_st, const int* __restrict__ asp_len,
    const int* __restrict__ opi_st, const int* __restrict__ opi_len,
    const int* __restrict__ sent, const float* __restrict__ W_trip,
    const float* __restrict__ b_trip, const float* __restrict__ W_attn)
{
    int blk = blockIdx.x, tid = threadIdx.x;
    if (blk >= 8192) {
        copyBlk((float4*)out, (const float4*)emb, CPY_A + (blk - 8192), tid);
        return;
    }
    int half = tid >> 7;
    int hh = tid & 127;
    int row = blk * 2 + half;
    int b = row >> 9;
    const float2* Yb = (const float2*)(g_Y + (size_t)b * TT * 512);

    int ast = asp_st[row], aln = asp_len[row];
    int ost = opi_st[row], oln = opi_len[row];

    float2 asum = make_float2(0.f, 0.f);
#pragma unroll 4
    for (int k = 0; k <= aln; k++) {
        float2 v = Yb[(size_t)(ast + k) * 256 + hh];
        asum.x += v.x; asum.y += v.y;
    }
    float2 osum = make_float2(0.f, 0.f);
#pragma unroll 4
    for (int k = 0; k <= oln; k++) {
        float2 v = Yb[(size_t)(ost + k) * 256 + 128 + hh];
        osum.x += v.x; osum.y += v.y;
    }
    float ia = 1.f / (float)(aln + 1), io = 1.f / (float)(oln + 1);
    int sid = sent[row];
    float2 wt = ((const float2*)W_trip)[(size_t)(512 + sid) * 128 + hh];
    float2 bt = ((const float2*)b_trip)[hh];
    float2 v2;
    v2.x = asum.x * ia + osum.x * io + wt.x + bt.x;
    v2.y = asum.y * ia + osum.y * io + wt.y + bt.y;
    ((float2*)g_node)[((size_t)row << 7) + hh] = v2;

    float lx = (v2.x >= 0.f) ? v2.x : SLOPE * v2.x;
    float ly = (v2.y >= 0.f) ? v2.y : SLOPE * v2.y;
    float2 wa_t = ((const float2*)W_attn)[hh];
    float2 wa_s = ((const float2*)W_attn)[128 + hh];
    float at = lx * wa_t.x + ly * wa_t.y;
    float as = lx * wa_s.x + ly * wa_s.y;
#pragma unroll
    for (int o = 16; o; o >>= 1) {
        at += __shfl_xor_sync(0xffffffffu, at, o);
        as += __shfl_xor_sync(0xffffffffu, as, o);
    }
    __shared__ float sAt[8], sAs[8];
    int w = tid >> 5;
    if ((tid & 31) == 0) { sAt[w] = at; sAs[w] = as; }
    __syncthreads();
    if (hh == 0) {
        int w0 = half * 4;
        float a = sAt[w0] + sAt[w0 + 1] + sAt[w0 + 2] + sAt[w0 + 3];
        float s2 = sAs[w0] + sAs[w0 + 1] + sAs[w0 + 2] + sAs[w0 + 3];
        g_AT[row] = a;
        g_AS[row] = s2;
    }
}

// ============================================================================
// L3: edge (warp-per-row) + copyC
// ============================================================================
__global__ __launch_bounds__(256) void edgeKernel(
    float* __restrict__ out, const float* __restrict__ emb,
    const float* __restrict__ b_attn)
{
    int blk = blockIdx.x, tid = threadIdx.x;
    if (blk >= 2048) {
        copyBlk((float4*)out, (const float4*)emb, CPY_A + CPY_B + (blk - 2048), tid);
        return;
    }
    __shared__ int   s_cand[8][WCAP];
    __shared__ float s_sc[8][WCAP];
    int warp = tid >> 5, lane = tid & 31;
    int row = blk * 8 + warp;
    int b = row >> 9, bs = b * Nc;

    int m1 = g_rowcnt[row];
    if (m1 == 0) {
        if (lane == 0) g_hn[row] = 0;
        return;
    }
    if (m1 > WCAP) m1 = WCAP;
    int off = g_rowoff[row];
    for (int e = lane; e < m1; e += 32) s_cand[warp][e] = g_cand[off + e];

    const float* rp = g_node + ((size_t)row << 8);
    float nT[8];
#pragma unroll
    for (int k = 0; k < 8; k++) nT[k] = rp[lane + 32 * k];
    __syncwarp();

    float atv = g_AT[row], bat = b_attn[0];
    int m2 = 0;
    for (int e = 0; e < m1; e++) {
        int cd = s_cand[warp][e];
        int s = cd & 0xffff;
        const float* ns = g_node + ((size_t)(bs + s) << 8);
        float d = 0.f;
#pragma unroll
        for (int k = 0; k < 8; k++) d += nT[k] * ns[lane + 32 * k];
#pragma unroll
        for (int o = 16; o; o >>= 1) d += __shfl_xor_sync(0xffffffffu, d, o);
        if (lane == 0) {
            if (d > 0.f) { s_sc[warp][e] = atv + g_AS[bs + s] + g_AE[cd >> 16] + bat; m2++; }
            else s_sc[warp][e] = NEGINF;
        }
    }
    m2 = __shfl_sync(0xffffffffu, m2, 0);
    float invden = 0.f;
    if (lane == 0) {
        g_hn[row] = (m2 > 0) ? 1 : 0;
        if (m2 > 0) {
            atomicOr(&g_bhas[b], 1);
            int p = atomicAdd(&g_nact, 1);
            g_rows[p] = row;
            float mx = NEGINF;
            for (int e = 0; e < m1; e++) mx = fmaxf(mx, s_sc[warp][e]);
            float den = 0.f, w0 = 0.f, w1 = 0.f;
            for (int e = 0; e < m1; e++) {
                float we = expf(s_sc[warp][e] - mx);
                s_sc[warp][e] = we;
                den += we;
                if ((s_cand[warp][e] >> 16) == 0) w0 += we; else w1 += we;
            }
            invden = 1.f / den;
            g_w0[row] = w0 / den;
            g_w1[row] = w1 / den;
        }
    }
    invden = __shfl_sync(0xffffffffu, invden, 0);
    __syncwarp();
    if (m2 > 0) {
        float acc[8];
#pragma unroll
        for (int k = 0; k < 8; k++) acc[k] = 0.f;
        for (int e = 0; e < m1; e++) {
            float we = s_sc[warp][e];
            if (we != 0.f) {
                int s = s_cand[warp][e] & 0xffff;
                const float* ns = g_node + ((size_t)(bs + s) << 8);
#pragma unroll
                for (int k = 0; k < 8; k++) acc[k] += we * ns[lane + 32 * k];
            }
        }
        float* ag = g_agg + ((size_t)row << 8);
#pragma unroll
        for (int k = 0; k < 8; k++) ag[lane + 32 * k] = acc[k] * invden;
    }
}

// ============================================================================
// L4: GEMM1 via tf32 mma.sync — double-buffered smem, 1 sync/chunk, 2 blocks/SM
// ============================================================================
#define AS_STRIDE 20
#define BS_STRIDE 264

__global__ __launch_bounds__(256, 2) void gemm1Kernel(
    const float* __restrict__ W, const float* __restrict__ bias)
{
    int nact = g_nact;
    int br = blockIdx.x;
    if (br * 64 >= nact) return;
    int nrows = nact - br * 64;
    if (nrows > 64) nrows = 64;

    __shared__ __align__(16) u32 As[2][64 * AS_STRIDE];
    __shared__ __align__(16) u32 Bs[2][16 * BS_STRIDE];
    __shared__ float sB[256], sE0[256], sE1[256];
    __shared__ int rows[64];

    int tid = threadIdx.x;
    int lane = tid & 31, wid = tid >> 5;
    int wm = wid & 3, wn = wid >> 2;

    if (tid < 64) rows[tid] = g_rows[br * 64 + (tid < nrows ? tid : nrows - 1)];
    sB[tid]  = bias[tid];
    sE0[tid] = g_E[0][tid];
    sE1[tid] = g_E[1][tid];
    __syncthreads();

    const float* Ap = g_agg + ((size_t)rows[tid >> 2] << 8) + (tid & 3) * 4;
    int asw = (tid >> 2) * AS_STRIDE + (tid & 3) * 4;
    int bkr = tid >> 4, bcg = (tid & 15) * 16;
    const float* Bp = W + (size_t)bkr * 256 + bcg;
    int bsw = bkr * BS_STRIDE + bcg;

    float C[16][4];
#pragma unroll
    for (int j = 0; j < 16; j++)
#pragma unroll
        for (int i = 0; i < 4; i++) C[j][i] = 0.f;

    int g = lane >> 2, cc = lane & 3;

    // preload chunk 0 into buffer 0
    {
        float4 av = *(const float4*)Ap;
        As[0][asw + 0] = f2tf32(av.x); As[0][asw + 1] = f2tf32(av.y);
        As[0][asw + 2] = f2tf32(av.z); As[0][asw + 3] = f2tf32(av.w);
#pragma unroll
        for (int l = 0; l < 4; l++) {
            float4 bv = *(const float4*)(Bp + l * 4);
            Bs[0][bsw + l * 4 + 0] = f2tf32(bv.x); Bs[0][bsw + l * 4 + 1] = f2tf32(bv.y);
            Bs[0][bsw + l * 4 + 2] = f2tf32(bv.z); Bs[0][bsw + l * 4 + 3] = f2tf32(bv.w);
        }
    }
    __syncthreads();

    for (int kc = 0; kc < 16; kc++) {
        int cur = kc & 1;
        float4 av; float4 bv[4];
        bool more = (kc < 15);
        if (more) {
            av = *(const float4*)(Ap + (kc + 1) * 16);
            const float* bp = Bp + (size_t)((kc + 1) * 16) * 256;
#pragma unroll
            for (int l = 0; l < 4; l++) bv[l] = *(const float4*)(bp + l * 4);
        }
#pragma unroll
        for (int ks = 0; ks < 16; ks += 8) {
            u32 a0 = As[cur][(wm * 16 + g)     * AS_STRIDE + ks + cc];
            u32 a1 = As[cur][(wm * 16 + g + 8) * AS_STRIDE + ks + cc];
            u32 a2 = As[cur][(wm * 16 + g)     * AS_STRIDE + ks + cc + 4];
            u32 a3 = As[cur][(wm * 16 + g + 8) * AS_STRIDE + ks + cc + 4];
            const u32* b0p = &Bs[cur][(ks + cc)     * BS_STRIDE + wn * 128 + g];
            const u32* b1p = &Bs[cur][(ks + cc + 4) * BS_STRIDE + wn * 128 + g];
#pragma unroll
            for (int j = 0; j < 16; j++) {
                u32 b0 = b0p[j * 8];
                u32 b1 = b1p[j * 8];
                asm volatile(
                    "mma.sync.aligned.m16n8k8.row.col.f32.tf32.tf32.f32 "
                    "{%0,%1,%2,%3}, {%4,%5,%6,%7}, {%8,%9}, {%0,%1,%2,%3};"
                    : "+f"(C[j][0]), "+f"(C[j][1]), "+f"(C[j][2]), "+f"(C[j][3])
                    : "r"(a0), "r"(a1), "r"(a2), "r"(a3), "r"(b0), "r"(b1));
            }
        }
        if (more) {
            int nxt = cur ^ 1;
            As[nxt][asw + 0] = f2tf32(av.x); As[nxt][asw + 1] = f2tf32(av.y);
            As[nxt][asw + 2] = f2tf32(av.z); As[nxt][asw + 3] = f2tf32(av.w);
#pragma unroll
            for (int l = 0; l < 4; l++) {
                Bs[nxt][bsw + l * 4 + 0] = f2tf32(bv[l].x);
                Bs[nxt][bsw + l * 4 + 1] = f2tf32(bv[l].y);
                Bs[nxt][bsw + l * 4 + 2] = f2tf32(bv[l].z);
                Bs[nxt][bsw + l * 4 + 3] = f2tf32(bv[l].w);
            }
            __syncthreads();
        }
    }

    // epilogue: two rows per thread (g, g+8)
    int idx0 = wm * 16 + g, idx1 = idx0 + 8;
    bool ok0 = idx0 < nrows, ok1 = idx1 < nrows;
    int r0 = rows[idx0], r1 = rows[idx1];
    float w00 = g_w0[r0], w01 = g_w1[r0];
    float w10 = g_w0[r1], w11 = g_w1[r1];
#pragma unroll
    for (int j = 0; j < 16; j++) {
        int col = wn * 128 + j * 8 + 2 * cc;
        float bx = sB[col],     e0x = sE0[col],     e1x = sE1[col];
        float by = sB[col + 1], e0y = sE0[col + 1], e1y = sE1[col + 1];
        if (ok0) {
            float2 st;
            st.x = fmaxf(C[j][0] + bx + w00 * e0x + w01 * e1x, 0.f);
            st.y = fmaxf(C[j][1] + by + w00 * e0y + w01 * e1y, 0.f);
            *(float2*)&g_add[((size_t)r0 << 8) + col] = st;
        }
        if (ok1) {
            float2 st;
            st.x = fmaxf(C[j][2] + bx + w10 * e0x + w11 * e1x, 0.f);
            st.y = fmaxf(C[j][3] + by + w10 * e0y + w11 * e1y, 0.f);
            *(float2*)&g_add[((size_t)r1 << 8) + col] = st;
        }
    }
}

// ============================================================================
// L5: scatter via precomputed center lists
// ============================================================================
__global__ __launch_bounds__(256) void scatterKernel(float* __restrict__ out)
{
    int b = blockIdx.x >> 7;
    int c = blockIdx.x & 127;
    int h = threadIdx.x;
    if (!g_bhas[b]) return;
    int cnt = g_ccnt[b * 128 + c];
    if (cnt == 0) return;
    const int* list = g_clist + ((size_t)(b * 128 + c) << 9);
    float s = 0.f;
    for (int i = 0; i < cnt; i++) {
        int r = b * Nc + list[i];
        size_t o = ((size_t)r << 8) + h;
        s += g_hn[r] ? g_add[o] : g_node[o];
    }
    out[((size_t)b * Lc + c) * Hc + h] += s;
}

// ---------------- launch -----------------------------------------------------
extern "C" void kernel_launch(void* const* d_in, const int* in_sizes, int n_in,
                              void* d_out, int out_size)
{
    const float* emb     = (const float*)d_in[0];
    const float* W_trip  = (const float*)d_in[1];
    const float* b_trip  = (const float*)d_in[2];
    const float* edge_e  = (const float*)d_in[3];
    const float* W_attn  = (const float*)d_in[4];
    const float* b_attn  = (const float*)d_in[5];
    const float* W_gat   = (const float*)d_in[6];
    const float* b_gat   = (const float*)d_in[7];
    const int*   asp_st  = (const int*)d_in[8];
    const int*   asp_len = (const int*)d_in[9];
    const int*   opi_st  = (const int*)d_in[10];
    const int*   opi_len = (const int*)d_in[11];
    const int*   sent_id = (const int*)d_in[12];
    float* out = (float*)d_out;

    mega0Kernel<<<168 + CPY_A, 256>>>(out, emb, W_trip, asp_st, asp_len,
                                      opi_st, opi_len, edge_e, W_attn, W_gat);
    nodeStatsKernel<<<8192 + CPY_B, 256>>>(out, emb, asp_st, asp_len, opi_st, opi_len,
                                           sent_id, W_trip, b_trip, W_attn);
    edgeKernel<<<2048 + CPY_C, 256>>>(out, emb, b_attn);
    gemm1Kernel<<<256, 256>>>(W_gat, b_gat);
    scatterKernel<<<Bc * 128, 256>>>(out);
}

// round 8
// speedup vs baseline: 1.2602x; 1.0554x over previous
#include <cuda_runtime.h>
#include <cstdint>

#define Bc 32
#define Lc 4096
#define Hc 256
#define Nc 512
#define NROWS (Bc * Nc)          // 16384
#define TT 136
#define PROWS (Bc * TT)          // 4352
#define SLOPE 0.2f
#define NEGINF (-3.4028234663852886e38f)
#define EDGECAP (Nc * (Nc - 1) * 2)
#define WCAP 256

// copy partition: 8,388,608 float4 = 2048 blocks x 4096 float4
#define CPY_A 512   // mega0      chunks [0, 512)
#define CPY_B 640   // nodeStats  chunks [512, 1152)
#define CPY_C 512   // edge       chunks [1152, 1664)
#define CPY_D 384   // gemm1      chunks [1664, 2048)

typedef unsigned long long u64;
typedef unsigned int u32;

// ---------------- scratch ----------------
__device__ __align__(16) float g_Y[(size_t)PROWS * 512];
__device__ __align__(16) float g_node[(size_t)NROWS * 256];
__device__ __align__(16) float g_agg[(size_t)NROWS * 256];
__device__ __align__(16) float g_add[(size_t)NROWS * 256];
__device__ float g_AT[NROWS];
__device__ float g_AS[NROWS];
__device__ float g_AE[2];
__device__ float g_E[2][256];
__device__ float g_w0[NROWS];
__device__ float g_w1[NROWS];
__device__ int   g_hn[NROWS];
__device__ int   g_bhas[Bc];
__device__ int   g_rowcnt[NROWS];
__device__ int   g_rowoff[NROWS];
__device__ int   g_cand[(size_t)Bc * EDGECAP];
__device__ int   g_rows[NROWS];
__device__ int   g_nact;
__device__ int   g_clist[(size_t)Bc * 128 * 512];
__device__ int   g_ccnt[Bc * 128];

// ---------------- helpers ----------------
__device__ __forceinline__ u64 bcast2(float x) {
    u64 r; unsigned xi = __float_as_uint(x);
    asm("mov.b64 %0, {%1, %1};" : "=l"(r) : "r"(xi));
    return r;
}
__device__ __forceinline__ void ffma2(u64& d, u64 a, u64 b) {
    asm("fma.rn.f32x2 %0, %1, %2, %0;" : "+l"(d) : "l"(a), "l"(b));
}
__device__ __forceinline__ float2 unpk2(u64 v) {
    float2 r;
    asm("mov.b64 {%0, %1}, %2;" : "=f"(r.x), "=f"(r.y) : "l"(v));
    return r;
}
__device__ __forceinline__ u32 f2tf32(float f) {
    u32 r;
    asm("cvt.rna.tf32.f32 %0, %1;" : "=r"(r) : "f"(f));
    return r;
}

// ---------------- embedded copy block: 4096 float4 ----------------
__device__ __forceinline__ void copyBlk(float4* __restrict__ dst,
                                        const float4* __restrict__ src,
                                        int cblk, int tid)
{
    size_t base = ((size_t)cblk << 12) + tid;
#pragma unroll
    for (int i = 0; i < 16; i++) dst[base + (i << 8)] = src[base + (i << 8)];
}

// ============================================================================
// L1: gemm0 (blocks 0..135, 128x128 FFMA2, double-buffered k16) + build + copyA
// ============================================================================
__global__ __launch_bounds__(256) void mega0Kernel(
    float* __restrict__ out, const float* __restrict__ emb,
    const float* __restrict__ W_trip,
    const int* __restrict__ asp_st, const int* __restrict__ asp_len,
    const int* __restrict__ opi_st, const int* __restrict__ opi_len,
    const float* __restrict__ edge_emb, const float* __restrict__ W_attn,
    const float* __restrict__ W_gat)
{
    int blk = blockIdx.x, tid = threadIdx.x;

    if (blk >= 168) {
        copyBlk((float4*)out, (const float4*)emb, blk - 168, tid);
        return;
    }

    if (blk < 136) {    // gemm0: Y = emb_tok[4352,256] @ Wcat[256,512]
        __shared__ __align__(16) float As[2][16][128];
        __shared__ __align__(16) float Bs[2][16][128];
        int bc = blk & 3, br = blk >> 2;
        int aRow = tid >> 1, aHalf = (tid & 1) * 8;
        int bRow = tid >> 4, bCol = (tid & 15) * 8;

        int r = br * 128 + aRow;
        int b = r / TT;
        int t = r - b * TT;
        const float* Aptr = emb + ((size_t)(b * Lc + t)) * 256 + aHalf;
        int j = bc * 128 + bCol;
        int half = (j >= 256);
        const float* Bptr = W_trip + (size_t)(half * 256 + bRow) * 256 + (j & 255);

        u64 acc2[4][8];
#pragma unroll
        for (int i = 0; i < 4; i++)
#pragma unroll
            for (int jj = 0; jj < 8; jj++) acc2[i][jj] = 0ull;

        int trow = (tid >> 4) * 8;
        int tcol = (tid & 15) * 8;

        float aR[8], bR[8];
        *(float4*)&aR[0] = *(const float4*)(Aptr);
        *(float4*)&aR[4] = *(const float4*)(Aptr + 4);
        *(float4*)&bR[0] = *(const float4*)(Bptr);
        *(float4*)&bR[4] = *(const float4*)(Bptr + 4);
#pragma unroll
        for (int i = 0; i < 8; i++) As[0][aHalf + i][aRow] = aR[i];
        *(float4*)&Bs[0][bRow][bCol]     = *(float4*)&bR[0];
        *(float4*)&Bs[0][bRow][bCol + 4] = *(float4*)&bR[4];
        __syncthreads();

        for (int kc = 0; kc < 16; kc++) {
            int cur = kc & 1;
            bool more = (kc < 15);
            if (more) {
                const float* ap = Aptr + (kc + 1) * 16;
                *(float4*)&aR[0] = *(const float4*)ap;
                *(float4*)&aR[4] = *(const float4*)(ap + 4);
                const float* bp = Bptr + (size_t)((kc + 1) * 16) * 256;
                *(float4*)&bR[0] = *(const float4*)bp;
                *(float4*)&bR[4] = *(const float4*)(bp + 4);
            }
#pragma unroll
            for (int k = 0; k < 16; k++) {
                const u64* a64 = (const u64*)&As[cur][k][trow];
                u64 a2[4] = { a64[0], a64[1], a64[2], a64[3] };
                float bb[8];
                *(float4*)&bb[0] = *(const float4*)&Bs[cur][k][tcol];
                *(float4*)&bb[4] = *(const float4*)&Bs[cur][k][tcol + 4];
                u64 b2[8];
#pragma unroll
                for (int jj = 0; jj < 8; jj++) b2[jj] = bcast2(bb[jj]);
#pragma unroll
                for (int i = 0; i < 4; i++)
#pragma unroll
                    for (int jj = 0; jj < 8; jj++) ffma2(acc2[i][jj], a2[i], b2[jj]);
            }
            if (more) {
                int nxt = cur ^ 1;
#pragma unroll
                for (int i = 0; i < 8; i++) As[nxt][aHalf + i][aRow] = aR[i];
                *(float4*)&Bs[nxt][bRow][bCol]     = *(float4*)&bR[0];
                *(float4*)&Bs[nxt][bRow][bCol + 4] = *(float4*)&bR[4];
                __syncthreads();
            }
        }
#pragma unroll
        for (int i2 = 0; i2 < 4; i2++) {
            int r0 = br * 128 + trow + 2 * i2;
#pragma unroll
            for (int jj = 0; jj < 8; jj++) {
                float2 v = unpk2(acc2[i2][jj]);
                int c = bc * 128 + tcol + jj;
                g_Y[(size_t)r0 * 512 + c]       = v.x;
                g_Y[(size_t)(r0 + 1) * 512 + c] = v.y;
            }
        }
        return;
    }

    // ---- build: per-batch CSR + center lists + misc scalars ----
    {
        int bb = blk - 136;
        int base = bb * Nc;
        __shared__ int ka[512], ko[512], cen[512];
        __shared__ int wsum[8];
        __shared__ int sc_cnt[128];
        for (int i = tid; i < 512; i += 256) {
            int st = asp_st[base + i], ln = asp_len[base + i];
            int so = opi_st[base + i], lo = opi_len[base + i];
            ka[i] = st | (ln << 16);
            ko[i] = so | (lo << 16);
            cen[i] = (st + so) >> 1;
        }
        if (tid < 128) sc_cnt[tid] = 0;
        __syncthreads();

        int t0 = 2 * tid, t1 = t0 + 1;
        int ka0 = ka[t0], ko0 = ko[t0], ce0 = cen[t0];
        int ka1 = ka[t1], ko1 = ko[t1], ce1 = cen[t1];
        int c0 = 0, c1 = 0, r0 = 0, r1 = 0;
        for (int s = 0; s < 512; s++) {
            int kas = ka[s], kos = ko[s], ces = cen[s];
            if (s != t0) c0 += (kas == ka0) + (kos == ko0);
            if (s != t1) c1 += (kas == ka1) + (kos == ko1);
            r0 += (s < t0 && ces == ce0);
            r1 += (s < t1 && ces == ce1);
        }
        int ps = c0 + c1;
        int lane = tid & 31, w = tid >> 5;
        int v = ps;
#pragma unroll
        for (int o = 1; o < 32; o <<= 1) {
            int n = __shfl_up_sync(0xffffffffu, v, o);
            if (lane >= o) v += n;
        }
        if (lane == 31) wsum[w] = v;
        __syncthreads();
        if (tid == 0) {
            int run = 0;
#pragma unroll
            for (int i = 0; i < 8; i++) { int x = wsum[i]; wsum[i] = run; run += x; }
        }
        __syncthreads();
        int off = v - ps + wsum[w];
        g_rowcnt[base + t0] = c0;
        g_rowcnt[base + t1] = c1;
        int p0 = bb * EDGECAP + off;
        int p1 = p0 + c0;
        g_rowoff[base + t0] = p0;
        g_rowoff[base + t1] = p1;
        for (int s = 0; s < 512; s++) {
            int kas = ka[s], kos = ko[s];
            if (s != t0) {
                if (kas == ka0) g_cand[p0++] = s;
                if (kos == ko0) g_cand[p0++] = s | (1 << 16);
            }
            if (s != t1) {
                if (kas == ka1) g_cand[p1++] = s;
                if (kos == ko1) g_cand[p1++] = s | (1 << 16);
            }
        }
        g_clist[((size_t)(bb * 128 + ce0) << 9) + r0] = t0;
        g_clist[((size_t)(bb * 128 + ce1) << 9) + r1] = t1;
        atomicAdd(&sc_cnt[ce0], 1);
        atomicAdd(&sc_cnt[ce1], 1);
        __syncthreads();
        if (tid < 128) g_ccnt[bb * 128 + tid] = sc_cnt[tid];

        if (bb == 0) {
            int h = tid;
#pragma unroll
            for (int e = 0; e < 2; e++) {
                float s = 0.f;
                for (int k = 0; k < 256; k++)
                    s += edge_emb[e * 256 + k] * W_gat[(size_t)(256 + k) * 256 + h];
                g_E[e][h] = s;
            }
            if (tid < 2) {
                float sa = 0.f;
                for (int k = 0; k < 256; k++) {
                    float vv = edge_emb[tid * 256 + k];
                    vv = (vv >= 0.f) ? vv : SLOPE * vv;
                    sa += vv * W_attn[512 + k];
                }
                g_AE[tid] = sa;
            }
            if (tid >= 4 && tid < 4 + Bc) g_bhas[tid - 4] = 0;
            if (tid == 2) g_nact = 0;
        }
    }
}

// ============================================================================
// L2: nodeStats (blocks 0..8191, 2 rows/block, float2) + copyB
// ============================================================================
__global__ __launch_bounds__(256) void nodeStatsKernel(
    float* __restrict__ out, const float* __restrict__ emb,
    const int* __restrict__ asp_st, const int* __restrict__ asp_len,
    const int* __restrict__ opi_st, const int* __restrict__ opi_len,
    const int* __restrict__ sent, const float* __restrict__ W_trip,
    const float* __restrict__ b_trip, const float* __restrict__ W_attn)
{
    int blk = blockIdx.x, tid = threadIdx.x;
    if (blk >= 8192) {
        copyBlk((float4*)out, (const float4*)emb, CPY_A + (blk - 8192), tid);
        return;
    }
    int half = tid >> 7;
    int hh = tid & 127;
    int row = blk * 2 + half;
    int b = row >> 9;
    const float2* Yb = (const float2*)(g_Y + (size_t)b * TT * 512);

    int ast = asp_st[row], aln = asp_len[row];
    int ost = opi_st[row], oln = opi_len[row];

    float2 asum = make_float2(0.f, 0.f);
#pragma unroll 4
    for (int k = 0; k <= aln; k++) {
        float2 v = Yb[(size_t)(ast + k) * 256 + hh];
        asum.x += v.x; asum.y += v.y;
    }
    float2 osum = make_float2(0.f, 0.f);
#pragma unroll 4
    for (int k = 0; k <= oln; k++) {
        float2 v = Yb[(size_t)(ost + k) * 256 + 128 + hh];
        osum.x += v.x; osum.y += v.y;
    }
    float ia = 1.f / (float)(aln + 1), io = 1.f / (float)(oln + 1);
    int sid = sent[row];
    float2 wt = ((const float2*)W_trip)[(size_t)(512 + sid) * 128 + hh];
    float2 bt = ((const float2*)b_trip)[hh];
    float2 v2;
    v2.x = asum.x * ia + osum.x * io + wt.x + bt.x;
    v2.y = asum.y * ia + osum.y * io + wt.y + bt.y;
    ((float2*)g_node)[((size_t)row << 7) + hh] = v2;

    float lx = (v2.x >= 0.f) ? v2.x : SLOPE * v2.x;
    float ly = (v2.y >= 0.f) ? v2.y : SLOPE * v2.y;
    float2 wa_t = ((const float2*)W_attn)[hh];
    float2 wa_s = ((const float2*)W_attn)[128 + hh];
    float at = lx * wa_t.x + ly * wa_t.y;
    float as = lx * wa_s.x + ly * wa_s.y;
#pragma unroll
    for (int o = 16; o; o >>= 1) {
        at += __shfl_xor_sync(0xffffffffu, at, o);
        as += __shfl_xor_sync(0xffffffffu, as, o);
    }
    __shared__ float sAt[8], sAs[8];
    int w = tid >> 5;
    if ((tid & 31) == 0) { sAt[w] = at; sAs[w] = as; }
    __syncthreads();
    if (hh == 0) {
        int w0 = half * 4;
        float a = sAt[w0] + sAt[w0 + 1] + sAt[w0 + 2] + sAt[w0 + 3];
        float s2 = sAs[w0] + sAs[w0 + 1] + sAs[w0 + 2] + sAs[w0 + 3];
        g_AT[row] = a;
        g_AS[row] = s2;
    }
}

// ============================================================================
// L3: edge (warp-per-row) + copyC
// ============================================================================
__global__ __launch_bounds__(256) void edgeKernel(
    float* __restrict__ out, const float* __restrict__ emb,
    const float* __restrict__ b_attn)
{
    int blk = blockIdx.x, tid = threadIdx.x;
    if (blk >= 2048) {
        copyBlk((float4*)out, (const float4*)emb, CPY_A + CPY_B + (blk - 2048), tid);
        return;
    }
    __shared__ int   s_cand[8][WCAP];
    __shared__ float s_sc[8][WCAP];
    int warp = tid >> 5, lane = tid & 31;
    int row = blk * 8 + warp;
    int b = row >> 9, bs = b * Nc;

    int m1 = g_rowcnt[row];
    if (m1 == 0) {
        if (lane == 0) g_hn[row] = 0;
        return;
    }
    if (m1 > WCAP) m1 = WCAP;
    int off = g_rowoff[row];
    for (int e = lane; e < m1; e += 32) s_cand[warp][e] = g_cand[off + e];

    const float* rp = g_node + ((size_t)row << 8);
    float nT[8];
#pragma unroll
    for (int k = 0; k < 8; k++) nT[k] = rp[lane + 32 * k];
    __syncwarp();

    float atv = g_AT[row], bat = b_attn[0];
    int m2 = 0;
    for (int e = 0; e < m1; e++) {
        int cd = s_cand[warp][e];
        int s = cd & 0xffff;
        const float* ns = g_node + ((size_t)(bs + s) << 8);
        float d = 0.f;
#pragma unroll
        for (int k = 0; k < 8; k++) d += nT[k] * ns[lane + 32 * k];
#pragma unroll
        for (int o = 16; o; o >>= 1) d += __shfl_xor_sync(0xffffffffu, d, o);
        if (lane == 0) {
            if (d > 0.f) { s_sc[warp][e] = atv + g_AS[bs + s] + g_AE[cd >> 16] + bat; m2++; }
            else s_sc[warp][e] = NEGINF;
        }
    }
    m2 = __shfl_sync(0xffffffffu, m2, 0);
    float invden = 0.f;
    if (lane == 0) {
        g_hn[row] = (m2 > 0) ? 1 : 0;
        if (m2 > 0) {
            atomicOr(&g_bhas[b], 1);
            int p = atomicAdd(&g_nact, 1);
            g_rows[p] = row;
            float mx = NEGINF;
            for (int e = 0; e < m1; e++) mx = fmaxf(mx, s_sc[warp][e]);
            float den = 0.f, w0 = 0.f, w1 = 0.f;
            for (int e = 0; e < m1; e++) {
                float we = expf(s_sc[warp][e] - mx);
                s_sc[warp][e] = we;
                den += we;
                if ((s_cand[warp][e] >> 16) == 0) w0 += we; else w1 += we;
            }
            invden = 1.f / den;
            g_w0[row] = w0 / den;
            g_w1[row] = w1 / den;
        }
    }
    invden = __shfl_sync(0xffffffffu, invden, 0);
    __syncwarp();
    if (m2 > 0) {
        float acc[8];
#pragma unroll
        for (int k = 0; k < 8; k++) acc[k] = 0.f;
        for (int e = 0; e < m1; e++) {
            float we = s_sc[warp][e];
            if (we != 0.f) {
                int s = s_cand[warp][e] & 0xffff;
                const float* ns = g_node + ((size_t)(bs + s) << 8);
#pragma unroll
                for (int k = 0; k < 8; k++) acc[k] += we * ns[lane + 32 * k];
            }
        }
        float* ag = g_agg + ((size_t)row << 8);
#pragma unroll
        for (int k = 0; k < 8; k++) ag[lane + 32 * k] = acc[k] * invden;
    }
}

// ============================================================================
// L4: GEMM1 tf32 mma — 64x128 tiles (512 tile blocks) + copyD
// ============================================================================
#define AS_STRIDE 20
#define BS1_STRIDE 136

__global__ __launch_bounds__(256) void gemm1Kernel(
    float* __restrict__ out, const float* __restrict__ emb,
    const float* __restrict__ W, const float* __restrict__ bias)
{
    int blk = blockIdx.x, tid = threadIdx.x;
    if (blk >= 512) {
        copyBlk((float4*)out, (const float4*)emb,
                CPY_A + CPY_B + CPY_C + (blk - 512), tid);
        return;
    }
    int nact = g_nact;
    int bc = blk & 1, br = blk >> 1;
    if (br * 64 >= nact) return;
    int nrows = nact - br * 64;
    if (nrows > 64) nrows = 64;

    __shared__ __align__(16) u32 As[2][64 * AS_STRIDE];
    __shared__ __align__(16) u32 Bs[2][16 * BS1_STRIDE];
    __shared__ float sB[128], sE0[128], sE1[128];
    __shared__ int rows[64];

    int lane = tid & 31, wid = tid >> 5;
    int wm = wid & 3, wn = wid >> 2;   // wm: 16-row group, wn: 64-col group

    if (tid < 64) rows[tid] = g_rows[br * 64 + (tid < nrows ? tid : nrows - 1)];
    if (tid < 128) {
        int c = bc * 128 + tid;
        sB[tid]  = bias[c];
        sE0[tid] = g_E[0][c];
        sE1[tid] = g_E[1][c];
    }
    __syncthreads();

    const float* Ap = g_agg + ((size_t)rows[tid >> 2] << 8) + (tid & 3) * 4;
    int asw = (tid >> 2) * AS_STRIDE + (tid & 3) * 4;
    int bkr = tid >> 4, bcg = (tid & 15) * 8;
    const float* Bp = W + (size_t)bkr * 256 + bc * 128 + bcg;
    int bsw = bkr * BS1_STRIDE + bcg;

    float C[8][4];
#pragma unroll
    for (int j = 0; j < 8; j++)
#pragma unroll
        for (int i = 0; i < 4; i++) C[j][i] = 0.f;

    int g = lane >> 2, cc = lane & 3;

    // preload chunk 0
    {
        float4 av = *(const float4*)Ap;
        As[0][asw + 0] = f2tf32(av.x); As[0][asw + 1] = f2tf32(av.y);
        As[0][asw + 2] = f2tf32(av.z); As[0][asw + 3] = f2tf32(av.w);
#pragma unroll
        for (int l = 0; l < 2; l++) {
            float4 bv = *(const float4*)(Bp + l * 4);
            Bs[0][bsw + l * 4 + 0] = f2tf32(bv.x); Bs[0][bsw + l * 4 + 1] = f2tf32(bv.y);
            Bs[0][bsw + l * 4 + 2] = f2tf32(bv.z); Bs[0][bsw + l * 4 + 3] = f2tf32(bv.w);
        }
    }
    __syncthreads();

    for (int kc = 0; kc < 16; kc++) {
        int cur = kc & 1;
        float4 av; float4 bv[2];
        bool more = (kc < 15);
        if (more) {
            av = *(const float4*)(Ap + (kc + 1) * 16);
            const float* bp = Bp + (size_t)((kc + 1) * 16) * 256;
#pragma unroll
            for (int l = 0; l < 2; l++) bv[l] = *(const float4*)(bp + l * 4);
        }
#pragma unroll
        for (int ks = 0; ks < 16; ks += 8) {
            u32 a0 = As[cur][(wm * 16 + g)     * AS_STRIDE + ks + cc];
            u32 a1 = As[cur][(wm * 16 + g + 8) * AS_STRIDE + ks + cc];
            u32 a2 = As[cur][(wm * 16 + g)     * AS_STRIDE + ks + cc + 4];
            u32 a3 = As[cur][(wm * 16 + g + 8) * AS_STRIDE + ks + cc + 4];
            const u32* b0p = &Bs[cur][(ks + cc)     * BS1_STRIDE + wn * 64 + g];
            const u32* b1p = &Bs[cur][(ks + cc + 4) * BS1_STRIDE + wn * 64 + g];
#pragma unroll
            for (int j = 0; j < 8; j++) {
                u32 b0 = b0p[j * 8];
                u32 b1 = b1p[j * 8];
                asm volatile(
                    "mma.sync.aligned.m16n8k8.row.col.f32.tf32.tf32.f32 "
                    "{%0,%1,%2,%3}, {%4,%5,%6,%7}, {%8,%9}, {%0,%1,%2,%3};"
                    : "+f"(C[j][0]), "+f"(C[j][1]), "+f"(C[j][2]), "+f"(C[j][3])
                    : "r"(a0), "r"(a1), "r"(a2), "r"(a3), "r"(b0), "r"(b1));
            }
        }
        if (more) {
            int nxt = cur ^ 1;
            As[nxt][asw + 0] = f2tf32(av.x); As[nxt][asw + 1] = f2tf32(av.y);
            As[nxt][asw + 2] = f2tf32(av.z); As[nxt][asw + 3] = f2tf32(av.w);
#pragma unroll
            for (int l = 0; l < 2; l++) {
                Bs[nxt][bsw + l * 4 + 0] = f2tf32(bv[l].x);
                Bs[nxt][bsw + l * 4 + 1] = f2tf32(bv[l].y);
                Bs[nxt][bsw + l * 4 + 2] = f2tf32(bv[l].z);
                Bs[nxt][bsw + l * 4 + 3] = f2tf32(bv[l].w);
            }
            __syncthreads();
        }
    }

    // epilogue: two rows per thread (g, g+8)
    int idx0 = wm * 16 + g, idx1 = idx0 + 8;
    bool ok0 = idx0 < nrows, ok1 = idx1 < nrows;
    int r0 = rows[idx0], r1 = rows[idx1];
    float w00 = g_w0[r0], w01 = g_w1[r0];
    float w10 = g_w0[r1], w11 = g_w1[r1];
#pragma unroll
    for (int j = 0; j < 8; j++) {
        int lc = wn * 64 + j * 8 + 2 * cc;
        int col = bc * 128 + lc;
        float bx = sB[lc],     e0x = sE0[lc],     e1x = sE1[lc];
        float by = sB[lc + 1], e0y = sE0[lc + 1], e1y = sE1[lc + 1];
        if (ok0) {
            float2 st;
            st.x = fmaxf(C[j][0] + bx + w00 * e0x + w01 * e1x, 0.f);
            st.y = fmaxf(C[j][1] + by + w00 * e0y + w01 * e1y, 0.f);
            *(float2*)&g_add[((size_t)r0 << 8) + col] = st;
        }
        if (ok1) {
            float2 st;
            st.x = fmaxf(C[j][2] + bx + w10 * e0x + w11 * e1x, 0.f);
            st.y = fmaxf(C[j][3] + by + w10 * e0y + w11 * e1y, 0.f);
            *(float2*)&g_add[((size_t)r1 << 8) + col] = st;
        }
    }
}

// ============================================================================
// L5: scatter via precomputed center lists
// ============================================================================
__global__ __launch_bounds__(256) void scatterKernel(float* __restrict__ out)
{
    int b = blockIdx.x >> 7;
    int c = blockIdx.x & 127;
    int h = threadIdx.x;
    if (!g_bhas[b]) return;
    int cnt = g_ccnt[b * 128 + c];
    if (cnt == 0) return;
    const int* list = g_clist + ((size_t)(b * 128 + c) << 9);
    float s = 0.f;
    for (int i = 0; i < cnt; i++) {
        int r = b * Nc + list[i];
        size_t o = ((size_t)r << 8) + h;
        s += g_hn[r] ? g_add[o] : g_node[o];
    }
    out[((size_t)b * Lc + c) * Hc + h] += s;
}

// ---------------- launch -----------------------------------------------------
extern "C" void kernel_launch(void* const* d_in, const int* in_sizes, int n_in,
                              void* d_out, int out_size)
{
    const float* emb     = (const float*)d_in[0];
    const float* W_trip  = (const float*)d_in[1];
    const float* b_trip  = (const float*)d_in[2];
    const float* edge_e  = (const float*)d_in[3];
    const float* W_attn  = (const float*)d_in[4];
    const float* b_attn  = (const float*)d_in[5];
    const float* W_gat   = (const float*)d_in[6];
    const float* b_gat   = (const float*)d_in[7];
    const int*   asp_st  = (const int*)d_in[8];
    const int*   asp_len = (const int*)d_in[9];
    const int*   opi_st  = (const int*)d_in[10];
    const int*   opi_len = (const int*)d_in[11];
    const int*   sent_id = (const int*)d_in[12];
    float* out = (float*)d_out;

    mega0Kernel<<<168 + CPY_A, 256>>>(out, emb, W_trip, asp_st, asp_len,
                                      opi_st, opi_len, edge_e, W_attn, W_gat);
    nodeStatsKernel<<<8192 + CPY_B, 256>>>(out, emb, asp_st, asp_len, opi_st, opi_len,
                                           sent_id, W_trip, b_trip, W_attn);
    edgeKernel<<<2048 + CPY_C, 256>>>(out, emb, b_attn);
    gemm1Kernel<<<512 + CPY_D, 256>>>(out, emb, W_gat, b_gat);
    scatterKernel<<<Bc * 128, 256>>>(out);
}

// round 10
// speedup vs baseline: 1.3267x; 1.0528x over previous
#include <cuda_runtime.h>
#include <cstdint>

#define Bc 32
#define Lc 4096
#define Hc 256
#define Nc 512
#define NROWS (Bc * Nc)          // 16384
#define TT 136
#define PROWS (Bc * TT)          // 4352
#define SLOPE 0.2f
#define NEGINF (-3.4028234663852886e38f)
#define EDGECAP (Nc * (Nc - 1) * 2)
#define WCAP 256

// copy partition: 8,388,608 float4 = 2048 blocks x 4096 float4
#define CPY_A 512   // mega0
#define CPY_B 640   // nodeStats
#define CPY_C 512   // edge
#define CPY_D 384   // gemm1

typedef unsigned long long u64;
typedef unsigned int u32;

// ---------------- scratch ----------------
__device__ __align__(16) float g_Y[(size_t)PROWS * 512];
__device__ __align__(16) float g_node[(size_t)NROWS * 256];
__device__ __align__(16) float g_agg[(size_t)NROWS * 256];
__device__ __align__(16) float g_add[(size_t)NROWS * 256];
__device__ float g_AT[NROWS];
__device__ float g_AS[NROWS];
__device__ float g_AE[2];
__device__ float g_E[2][256];
__device__ float g_w0[NROWS];
__device__ float g_w1[NROWS];
__device__ int   g_hn[NROWS];
__device__ int   g_bhas[Bc];
__device__ int   g_rowcnt[NROWS];
__device__ int   g_rowoff[NROWS];
__device__ int   g_cand[(size_t)Bc * EDGECAP];
__device__ int   g_rows[NROWS];
__device__ int   g_nact;
__device__ int   g_clist[(size_t)Bc * 128 * 512];
__device__ int   g_ccnt[Bc * 128];

// ---------------- helpers ----------------
__device__ __forceinline__ u32 f2tf32(float f) {
    u32 r;
    asm("cvt.rna.tf32.f32 %0, %1;" : "=r"(r) : "f"(f));
    return r;
}
__device__ __forceinline__ void tf32split(float a, u32& hi, u32& lo) {
    hi = f2tf32(a);
    lo = f2tf32(a - __uint_as_float(hi));
}

#define MMA_TF32(C0, C1, C2, C3, A0, A1, A2, A3, B0, B1)                        \
    asm volatile(                                                                \
        "mma.sync.aligned.m16n8k8.row.col.f32.tf32.tf32.f32 "                    \
        "{%0,%1,%2,%3}, {%4,%5,%6,%7}, {%8,%9}, {%0,%1,%2,%3};"                  \
        : "+f"(C0), "+f"(C1), "+f"(C2), "+f"(C3)                                 \
        : "r"(A0), "r"(A1), "r"(A2), "r"(A3), "r"(B0), "r"(B1))

// ---------------- embedded copy block: 4096 float4 ----------------
__device__ __forceinline__ void copyBlk(float4* __restrict__ dst,
                                        const float4* __restrict__ src,
                                        int cblk, int tid)
{
    size_t base = ((size_t)cblk << 12) + tid;
#pragma unroll
    for (int i = 0; i < 16; i++) dst[base + (i << 8)] = src[base + (i << 8)];
}

#define AS_STRIDE 20
#define BS_STRIDE 136

// ============================================================================
// L1: gemm0 tf32-split (blocks 0..271: 64x128 tiles, SINGLE-buffer Hi/Lo)
//     + build (272..303) + copyA
// Y[4352,512] = emb_tok @ Wcat, fp32-accurate via 3-MMA hi/lo split
// ============================================================================
__global__ __launch_bounds__(256) void mega0Kernel(
    float* __restrict__ out, const float* __restrict__ emb,
    const float* __restrict__ W_trip,
    const int* __restrict__ asp_st, const int* __restrict__ asp_len,
    const int* __restrict__ opi_st, const int* __restrict__ opi_len,
    const float* __restrict__ edge_emb, const float* __restrict__ W_attn,
    const float* __restrict__ W_gat)
{
    int blk = blockIdx.x, tid = threadIdx.x;

    if (blk >= 304) {
        copyBlk((float4*)out, (const float4*)emb, blk - 304, tid);
        return;
    }

    if (blk < 272) {
        __shared__ __align__(16) u32 AsH[64 * AS_STRIDE];
        __shared__ __align__(16) u32 AsL[64 * AS_STRIDE];
        __shared__ __align__(16) u32 BsH[16 * BS_STRIDE];
        __shared__ __align__(16) u32 BsL[16 * BS_STRIDE];

        int bc = blk & 3, br = blk >> 2;
        int lane = tid & 31, wid = tid >> 5;
        int wm = wid & 3, wn = wid >> 2;

        int aRow = tid >> 2;
        int r = br * 64 + aRow;
        int b = r / TT, t = r - b * TT;
        const float* Ap = emb + ((size_t)(b * Lc + t)) * 256 + (tid & 3) * 4;
        int asw = aRow * AS_STRIDE + (tid & 3) * 4;

        int bkr = tid >> 4, bcg = (tid & 15) * 8;
        int j0 = bc * 128 + bcg;
        int half = (j0 >= 256);
        const float* Bp = W_trip + (size_t)(half * 256 + bkr) * 256 + (j0 - half * 256);
        int bsw = bkr * BS_STRIDE + bcg;

        float C[8][4];
#pragma unroll
        for (int j = 0; j < 8; j++)
#pragma unroll
            for (int i = 0; i < 4; i++) C[j][i] = 0.f;

        int g = lane >> 2, cc = lane & 3;

        // preload chunk 0
        float4 av = *(const float4*)Ap;
        float4 bv[2];
        bv[0] = *(const float4*)Bp;
        bv[1] = *(const float4*)(Bp + 4);

        for (int kc = 0; kc < 16; kc++) {
            // store current chunk to smem
            {
                u32 h, l;
                tf32split(av.x, h, l); AsH[asw + 0] = h; AsL[asw + 0] = l;
                tf32split(av.y, h, l); AsH[asw + 1] = h; AsL[asw + 1] = l;
                tf32split(av.z, h, l); AsH[asw + 2] = h; AsL[asw + 2] = l;
                tf32split(av.w, h, l); AsH[asw + 3] = h; AsL[asw + 3] = l;
#pragma unroll
                for (int q = 0; q < 2; q++) {
                    tf32split(bv[q].x, h, l); BsH[bsw + q * 4 + 0] = h; BsL[bsw + q * 4 + 0] = l;
                    tf32split(bv[q].y, h, l); BsH[bsw + q * 4 + 1] = h; BsL[bsw + q * 4 + 1] = l;
                    tf32split(bv[q].z, h, l); BsH[bsw + q * 4 + 2] = h; BsL[bsw + q * 4 + 2] = l;
                    tf32split(bv[q].w, h, l); BsH[bsw + q * 4 + 3] = h; BsL[bsw + q * 4 + 3] = l;
                }
            }
            __syncthreads();
            // prefetch next chunk (loads issue before MMA phase)
            bool more = (kc < 15);
            if (more) {
                av = *(const float4*)(Ap + (kc + 1) * 16);
                const float* bp = Bp + (size_t)((kc + 1) * 16) * 256;
                bv[0] = *(const float4*)bp;
                bv[1] = *(const float4*)(bp + 4);
            }
#pragma unroll
            for (int ks = 0; ks < 16; ks += 8) {
                int ra = (wm * 16 + g) * AS_STRIDE + ks + cc;
                int rb = (wm * 16 + g + 8) * AS_STRIDE + ks + cc;
                u32 ah0 = AsH[ra],     ah1 = AsH[rb];
                u32 ah2 = AsH[ra + 4], ah3 = AsH[rb + 4];
                u32 al0 = AsL[ra],     al1 = AsL[rb];
                u32 al2 = AsL[ra + 4], al3 = AsL[rb + 4];
                const u32* bh0p = &BsH[(ks + cc)     * BS_STRIDE + wn * 64 + g];
                const u32* bh1p = &BsH[(ks + cc + 4) * BS_STRIDE + wn * 64 + g];
                const u32* bl0p = &BsL[(ks + cc)     * BS_STRIDE + wn * 64 + g];
                const u32* bl1p = &BsL[(ks + cc + 4) * BS_STRIDE + wn * 64 + g];
#pragma unroll
                for (int j = 0; j < 8; j++) {
                    u32 bh0 = bh0p[j * 8], bh1 = bh1p[j * 8];
                    u32 bl0 = bl0p[j * 8], bl1 = bl1p[j * 8];
                    MMA_TF32(C[j][0], C[j][1], C[j][2], C[j][3],
                             ah0, ah1, ah2, ah3, bh0, bh1);
                    MMA_TF32(C[j][0], C[j][1], C[j][2], C[j][3],
                             ah0, ah1, ah2, ah3, bl0, bl1);
                    MMA_TF32(C[j][0], C[j][1], C[j][2], C[j][3],
                             al0, al1, al2, al3, bh0, bh1);
                }
            }
            __syncthreads();
        }

        int rr0 = br * 64 + wm * 16 + g;
        int rr1 = rr0 + 8;
#pragma unroll
        for (int j = 0; j < 8; j++) {
            int col = bc * 128 + wn * 64 + j * 8 + 2 * cc;
            float2 v0 = make_float2(C[j][0], C[j][1]);
            float2 v1 = make_float2(C[j][2], C[j][3]);
            *(float2*)&g_Y[(size_t)rr0 * 512 + col] = v0;
            *(float2*)&g_Y[(size_t)rr1 * 512 + col] = v1;
        }
        return;
    }

    // ---- build: per-batch CSR + center lists + misc scalars ----
    {
        int bb = blk - 272;
        int base = bb * Nc;
        __shared__ int ka[512], ko[512], cen[512];
        __shared__ int wsum[8];
        __shared__ int sc_cnt[128];
        for (int i = tid; i < 512; i += 256) {
            int st = asp_st[base + i], ln = asp_len[base + i];
            int so = opi_st[base + i], lo = opi_len[base + i];
            ka[i] = st | (ln << 16);
            ko[i] = so | (lo << 16);
            cen[i] = (st + so) >> 1;
        }
        if (tid < 128) sc_cnt[tid] = 0;
        __syncthreads();

        int t0 = 2 * tid, t1 = t0 + 1;
        int ka0 = ka[t0], ko0 = ko[t0], ce0 = cen[t0];
        int ka1 = ka[t1], ko1 = ko[t1], ce1 = cen[t1];
        int c0 = 0, c1 = 0, r0 = 0, r1 = 0;
        for (int s = 0; s < 512; s++) {
            int kas = ka[s], kos = ko[s], ces = cen[s];
            if (s != t0) c0 += (kas == ka0) + (kos == ko0);
            if (s != t1) c1 += (kas == ka1) + (kos == ko1);
            r0 += (s < t0 && ces == ce0);
            r1 += (s < t1 && ces == ce1);
        }
        int ps = c0 + c1;
        int lane = tid & 31, w = tid >> 5;
        int v = ps;
#pragma unroll
        for (int o = 1; o < 32; o <<= 1) {
            int n = __shfl_up_sync(0xffffffffu, v, o);
            if (lane >= o) v += n;
        }
        if (lane == 31) wsum[w] = v;
        __syncthreads();
        if (tid == 0) {
            int run = 0;
#pragma unroll
            for (int i = 0; i < 8; i++) { int x = wsum[i]; wsum[i] = run; run += x; }
        }
        __syncthreads();
        int off = v - ps + wsum[w];
        g_rowcnt[base + t0] = c0;
        g_rowcnt[base + t1] = c1;
        int p0 = bb * EDGECAP + off;
        int p1 = p0 + c0;
        g_rowoff[base + t0] = p0;
        g_rowoff[base + t1] = p1;
        for (int s = 0; s < 512; s++) {
            int kas = ka[s], kos = ko[s];
            if (s != t0) {
                if (kas == ka0) g_cand[p0++] = s;
                if (kos == ko0) g_cand[p0++] = s | (1 << 16);
            }
            if (s != t1) {
                if (kas == ka1) g_cand[p1++] = s;
                if (kos == ko1) g_cand[p1++] = s | (1 << 16);
            }
        }
        g_clist[((size_t)(bb * 128 + ce0) << 9) + r0] = t0;
        g_clist[((size_t)(bb * 128 + ce1) << 9) + r1] = t1;
        atomicAdd(&sc_cnt[ce0], 1);
        atomicAdd(&sc_cnt[ce1], 1);
        __syncthreads();
        if (tid < 128) g_ccnt[bb * 128 + tid] = sc_cnt[tid];

        if (bb == 0) {
            int h = tid;
#pragma unroll
            for (int e = 0; e < 2; e++) {
                float s = 0.f;
                for (int k = 0; k < 256; k++)
                    s += edge_emb[e * 256 + k] * W_gat[(size_t)(256 + k) * 256 + h];
                g_E[e][h] = s;
            }
            if (tid < 2) {
                float sa = 0.f;
                for (int k = 0; k < 256; k++) {
                    float vv = edge_emb[tid * 256 + k];
                    vv = (vv >= 0.f) ? vv : SLOPE * vv;
                    sa += vv * W_attn[512 + k];
                }
                g_AE[tid] = sa;
            }
            if (tid >= 4 && tid < 4 + Bc) g_bhas[tid - 4] = 0;
            if (tid == 2) g_nact = 0;
        }
    }
}

// ============================================================================
// L2: nodeStats (blocks 0..4095, 4 rows/block, float4) + copyB
// ============================================================================
__global__ __launch_bounds__(256) void nodeStatsKernel(
    float* __restrict__ out, const float* __restrict__ emb,
    const int* __restrict__ asp_st, const int* __restrict__ asp_len,
    const int* __restrict__ opi_st, const int* __restrict__ opi_len,
    const int* __restrict__ sent, const float* __restrict__ W_trip,
    const float* __restrict__ b_trip, const float* __restrict__ W_attn)
{
    int blk = blockIdx.x, tid = threadIdx.x;
    if (blk >= 4096) {
        copyBlk((float4*)out, (const float4*)emb, CPY_A + (blk - 4096), tid);
        return;
    }
    int rib = tid >> 6;           // row in block 0..3
    int c4 = tid & 63;            // float4 column
    int row = blk * 4 + rib;
    int b = row >> 9;
    const float4* Yb = (const float4*)(g_Y + (size_t)b * TT * 512);

    int ast = asp_st[row], aln = asp_len[row];
    int ost = opi_st[row], oln = opi_len[row];

    float4 asum = make_float4(0.f, 0.f, 0.f, 0.f);
#pragma unroll 4
    for (int k = 0; k <= aln; k++) {
        float4 v = Yb[(size_t)(ast + k) * 128 + c4];
        asum.x += v.x; asum.y += v.y; asum.z += v.z; asum.w += v.w;
    }
    float4 osum = make_float4(0.f, 0.f, 0.f, 0.f);
#pragma unroll 4
    for (int k = 0; k <= oln; k++) {
        float4 v = Yb[(size_t)(ost + k) * 128 + 64 + c4];
        osum.x += v.x; osum.y += v.y; osum.z += v.z; osum.w += v.w;
    }
    float ia = 1.f / (float)(aln + 1), io = 1.f / (float)(oln + 1);
    int sid = sent[row];
    float4 wt = ((const float4*)W_trip)[(size_t)(512 + sid) * 64 + c4];
    float4 bt = ((const float4*)b_trip)[c4];
    float4 v4;
    v4.x = asum.x * ia + osum.x * io + wt.x + bt.x;
    v4.y = asum.y * ia + osum.y * io + wt.y + bt.y;
    v4.z = asum.z * ia + osum.z * io + wt.z + bt.z;
    v4.w = asum.w * ia + osum.w * io + wt.w + bt.w;
    ((float4*)g_node)[((size_t)row << 6) + c4] = v4;

    float4 lv;
    lv.x = (v4.x >= 0.f) ? v4.x : SLOPE * v4.x;
    lv.y = (v4.y >= 0.f) ? v4.y : SLOPE * v4.y;
    lv.z = (v4.z >= 0.f) ? v4.z : SLOPE * v4.z;
    lv.w = (v4.w >= 0.f) ? v4.w : SLOPE * v4.w;
    float4 wat = ((const float4*)W_attn)[c4];
    float4 was = ((const float4*)W_attn)[64 + c4];
    float at = lv.x * wat.x + lv.y * wat.y + lv.z * wat.z + lv.w * wat.w;
    float as = lv.x * was.x + lv.y * was.y + lv.z * was.z + lv.w * was.w;
#pragma unroll
    for (int o = 16; o; o >>= 1) {
        at += __shfl_xor_sync(0xffffffffu, at, o);
        as += __shfl_xor_sync(0xffffffffu, as, o);
    }
    __shared__ float sAt[8], sAs[8];
    int w = tid >> 5;
    if ((tid & 31) == 0) { sAt[w] = at; sAs[w] = as; }
    __syncthreads();
    if (c4 == 0) {
        int w0 = rib * 2;
        g_AT[row] = sAt[w0] + sAt[w0 + 1];
        g_AS[row] = sAs[w0] + sAs[w0 + 1];
    }
}

// ============================================================================
// L3: edge (warp-per-row) + copyC
// ============================================================================
__global__ __launch_bounds__(256) void edgeKernel(
    float* __restrict__ out, const float* __restrict__ emb,
    const float* __restrict__ b_attn)
{
    int blk = blockIdx.x, tid = threadIdx.x;
    if (blk >= 2048) {
        copyBlk((float4*)out, (const float4*)emb, CPY_A + CPY_B + (blk - 2048), tid);
        return;
    }
    __shared__ int   s_cand[8][WCAP];
    __shared__ float s_sc[8][WCAP];
    int warp = tid >> 5, lane = tid & 31;
    int row = blk * 8 + warp;
    int b = row >> 9, bs = b * Nc;

    int m1 = g_rowcnt[row];
    if (m1 == 0) {
        if (lane == 0) g_hn[row] = 0;
        return;
    }
    if (m1 > WCAP) m1 = WCAP;
    int off = g_rowoff[row];
    for (int e = lane; e < m1; e += 32) s_cand[warp][e] = g_cand[off + e];

    const float* rp = g_node + ((size_t)row << 8);
    float nT[8];
#pragma unroll
    for (int k = 0; k < 8; k++) nT[k] = rp[lane + 32 * k];
    __syncwarp();

    float atv = g_AT[row], bat = b_attn[0];
    int m2 = 0;
    for (int e = 0; e < m1; e++) {
        int cd = s_cand[warp][e];
        int s = cd & 0xffff;
        const float* ns = g_node + ((size_t)(bs + s) << 8);
        float d = 0.f;
#pragma unroll
        for (int k = 0; k < 8; k++) d += nT[k] * ns[lane + 32 * k];
#pragma unroll
        for (int o = 16; o; o >>= 1) d += __shfl_xor_sync(0xffffffffu, d, o);
        if (lane == 0) {
            if (d > 0.f) { s_sc[warp][e] = atv + g_AS[bs + s] + g_AE[cd >> 16] + bat; m2++; }
            else s_sc[warp][e] = NEGINF;
        }
    }
    m2 = __shfl_sync(0xffffffffu, m2, 0);
    float invden = 0.f;
    if (lane == 0) {
        g_hn[row] = (m2 > 0) ? 1 : 0;
        if (m2 > 0) {
            atomicOr(&g_bhas[b], 1);
            int p = atomicAdd(&g_nact, 1);
            g_rows[p] = row;
            float mx = NEGINF;
            for (int e = 0; e < m1; e++) mx = fmaxf(mx, s_sc[warp][e]);
            float den = 0.f, w0 = 0.f, w1 = 0.f;
            for (int e = 0; e < m1; e++) {
                float we = expf(s_sc[warp][e] - mx);
                s_sc[warp][e] = we;
                den += we;
                if ((s_cand[warp][e] >> 16) == 0) w0 += we; else w1 += we;
            }
            invden = 1.f / den;
            g_w0[row] = w0 / den;
            g_w1[row] = w1 / den;
        }
    }
    invden = __shfl_sync(0xffffffffu, invden, 0);
    __syncwarp();
    if (m2 > 0) {
        float acc[8];
#pragma unroll
        for (int k = 0; k < 8; k++) acc[k] = 0.f;
        for (int e = 0; e < m1; e++) {
            float we = s_sc[warp][e];
            if (we != 0.f) {
                int s = s_cand[warp][e] & 0xffff;
                const float* ns = g_node + ((size_t)(bs + s) << 8);
#pragma unroll
                for (int k = 0; k < 8; k++) acc[k] += we * ns[lane + 32 * k];
            }
        }
        float* ag = g_agg + ((size_t)row << 8);
#pragma unroll
        for (int k = 0; k < 8; k++) ag[lane + 32 * k] = acc[k] * invden;
    }
}

// ============================================================================
// L4: GEMM1 tf32 mma — 64x128 tiles (512 tile blocks), double buffer + copyD
// ============================================================================
__global__ __launch_bounds__(256) void gemm1Kernel(
    float* __restrict__ out, const float* __restrict__ emb,
    const float* __restrict__ W, const float* __restrict__ bias)
{
    int blk = blockIdx.x, tid = threadIdx.x;
    if (blk >= 512) {
        copyBlk((float4*)out, (const float4*)emb,
                CPY_A + CPY_B + CPY_C + (blk - 512), tid);
        return;
    }
    int nact = g_nact;
    int bc = blk & 1, br = blk >> 1;
    if (br * 64 >= nact) return;
    int nrows = nact - br * 64;
    if (nrows > 64) nrows = 64;

    __shared__ __align__(16) u32 As[2][64 * AS_STRIDE];
    __shared__ __align__(16) u32 Bs[2][16 * BS_STRIDE];
    __shared__ float sB[128], sE0[128], sE1[128];
    __shared__ int rows[64];

    int lane = tid & 31, wid = tid >> 5;
    int wm = wid & 3, wn = wid >> 2;

    if (tid < 64) rows[tid] = g_rows[br * 64 + (tid < nrows ? tid : nrows - 1)];
    if (tid < 128) {
        int c = bc * 128 + tid;
        sB[tid]  = bias[c];
        sE0[tid] = g_E[0][c];
        sE1[tid] = g_E[1][c];
    }
    __syncthreads();

    const float* Ap = g_agg + ((size_t)rows[tid >> 2] << 8) + (tid & 3) * 4;
    int asw = (tid >> 2) * AS_STRIDE + (tid & 3) * 4;
    int bkr = tid >> 4, bcg = (tid & 15) * 8;
    const float* Bp = W + (size_t)bkr * 256 + bc * 128 + bcg;
    int bsw = bkr * BS_STRIDE + bcg;

    float C[8][4];
#pragma unroll
    for (int j = 0; j < 8; j++)
#pragma unroll
        for (int i = 0; i < 4; i++) C[j][i] = 0.f;

    int g = lane >> 2, cc = lane & 3;

    {
        float4 av = *(const float4*)Ap;
        As[0][asw + 0] = f2tf32(av.x); As[0][asw + 1] = f2tf32(av.y);
        As[0][asw + 2] = f2tf32(av.z); As[0][asw + 3] = f2tf32(av.w);
#pragma unroll
        for (int l = 0; l < 2; l++) {
            float4 bv = *(const float4*)(Bp + l * 4);
            Bs[0][bsw + l * 4 + 0] = f2tf32(bv.x); Bs[0][bsw + l * 4 + 1] = f2tf32(bv.y);
            Bs[0][bsw + l * 4 + 2] = f2tf32(bv.z); Bs[0][bsw + l * 4 + 3] = f2tf32(bv.w);
        }
    }
    __syncthreads();

    for (int kc = 0; kc < 16; kc++) {
        int cur = kc & 1;
        float4 av; float4 bv[2];
        bool more = (kc < 15);
        if (more) {
            av = *(const float4*)(Ap + (kc + 1) * 16);
            const float* bp = Bp + (size_t)((kc + 1) * 16) * 256;
#pragma unroll
            for (int l = 0; l < 2; l++) bv[l] = *(const float4*)(bp + l * 4);
        }
#pragma unroll
        for (int ks = 0; ks < 16; ks += 8) {
            u32 a0 = As[cur][(wm * 16 + g)     * AS_STRIDE + ks + cc];
            u32 a1 = As[cur][(wm * 16 + g + 8) * AS_STRIDE + ks + cc];
            u32 a2 = As[cur][(wm * 16 + g)     * AS_STRIDE + ks + cc + 4];
            u32 a3 = As[cur][(wm * 16 + g + 8) * AS_STRIDE + ks + cc + 4];
            const u32* b0p = &Bs[cur][(ks + cc)     * BS_STRIDE + wn * 64 + g];
            const u32* b1p = &Bs[cur][(ks + cc + 4) * BS_STRIDE + wn * 64 + g];
#pragma unroll
            for (int j = 0; j < 8; j++) {
                u32 b0 = b0p[j * 8];
                u32 b1 = b1p[j * 8];
                MMA_TF32(C[j][0], C[j][1], C[j][2], C[j][3], a0, a1, a2, a3, b0, b1);
            }
        }
        if (more) {
            int nxt = cur ^ 1;
            As[nxt][asw + 0] = f2tf32(av.x); As[nxt][asw + 1] = f2tf32(av.y);
            As[nxt][asw + 2] = f2tf32(av.z); As[nxt][asw + 3] = f2tf32(av.w);
#pragma unroll
            for (int l = 0; l < 2; l++) {
                Bs[nxt][bsw + l * 4 + 0] = f2tf32(bv[l].x);
                Bs[nxt][bsw + l * 4 + 1] = f2tf32(bv[l].y);
                Bs[nxt][bsw + l * 4 + 2] = f2tf32(bv[l].z);
                Bs[nxt][bsw + l * 4 + 3] = f2tf32(bv[l].w);
            }
            __syncthreads();
        }
    }

    int idx0 = wm * 16 + g, idx1 = idx0 + 8;
    bool ok0 = idx0 < nrows, ok1 = idx1 < nrows;
    int r0 = rows[idx0], r1 = rows[idx1];
    float w00 = g_w0[r0], w01 = g_w1[r0];
    float w10 = g_w0[r1], w11 = g_w1[r1];
#pragma unroll
    for (int j = 0; j < 8; j++) {
        int lc = wn * 64 + j * 8 + 2 * cc;
        int col = bc * 128 + lc;
        float bx = sB[lc],     e0x = sE0[lc],     e1x = sE1[lc];
        float by = sB[lc + 1], e0y = sE0[lc + 1], e1y = sE1[lc + 1];
        if (ok0) {
            float2 st;
            st.x = fmaxf(C[j][0] + bx + w00 * e0x + w01 * e1x, 0.f);
            st.y = fmaxf(C[j][1] + by + w00 * e0y + w01 * e1y, 0.f);
            *(float2*)&g_add[((size_t)r0 << 8) + col] = st;
        }
        if (ok1) {
            float2 st;
            st.x = fmaxf(C[j][2] + bx + w10 * e0x + w11 * e1x, 0.f);
            st.y = fmaxf(C[j][3] + by + w10 * e0y + w11 * e1y, 0.f);
            *(float2*)&g_add[((size_t)r1 << 8) + col] = st;
        }
    }
}

// ============================================================================
// L5: scatter via precomputed center lists
// ============================================================================
__global__ __launch_bounds__(256) void scatterKernel(float* __restrict__ out)
{
    int b = blockIdx.x >> 7;
    int c = blockIdx.x & 127;
    int h = threadIdx.x;
    if (!g_bhas[b]) return;
    int cnt = g_ccnt[b * 128 + c];
    if (cnt == 0) return;
    const int* list = g_clist + ((size_t)(b * 128 + c) << 9);
    float s = 0.f;
    for (int i = 0; i < cnt; i++) {
        int r = b * Nc + list[i];
        size_t o = ((size_t)r << 8) + h;
        s += g_hn[r] ? g_add[o] : g_node[o];
    }
    out[((size_t)b * Lc + c) * Hc + h] += s;
}

// ---------------- launch -----------------------------------------------------
extern "C" void kernel_launch(void* const* d_in, const int* in_sizes, int n_in,
                              void* d_out, int out_size)
{
    const float* emb     = (const float*)d_in[0];
    const float* W_trip  = (const float*)d_in[1];
    const float* b_trip  = (const float*)d_in[2];
    const float* edge_e  = (const float*)d_in[3];
    const float* W_attn  = (const float*)d_in[4];
    const float* b_attn  = (const float*)d_in[5];
    const float* W_gat   = (const float*)d_in[6];
    const float* b_gat   = (const float*)d_in[7];
    const int*   asp_st  = (const int*)d_in[8];
    const int*   asp_len = (const int*)d_in[9];
    const int*   opi_st  = (const int*)d_in[10];
    const int*   opi_len = (const int*)d_in[11];
    const int*   sent_id = (const int*)d_in[12];
    float* out = (float*)d_out;

    mega0Kernel<<<304 + CPY_A, 256>>>(out, emb, W_trip, asp_st, asp_len,
                                      opi_st, opi_len, edge_e, W_attn, W_gat);
    nodeStatsKernel<<<4096 + CPY_B, 256>>>(out, emb, asp_st, asp_len, opi_st, opi_len,
                                           sent_id, W_trip, b_trip, W_attn);
    edgeKernel<<<2048 + CPY_C, 256>>>(out, emb, b_attn);
    gemm1Kernel<<<512 + CPY_D, 256>>>(out, emb, W_gat, b_gat);
    scatterKernel<<<Bc * 128, 256>>>(out);
}

// round 11
// speedup vs baseline: 1.3526x; 1.0195x over previous
#include <cuda_runtime.h>
#include <cstdint>

#define Bc 32
#define Lc 4096
#define Hc 256
#define Nc 512
#define NROWS (Bc * Nc)          // 16384
#define TT 136
#define PROWS (Bc * TT)          // 4352
#define SLOPE 0.2f
#define NEGINF (-3.4028234663852886e38f)
#define EDGECAP (Nc * (Nc - 1) * 2)
#define WCAP 256

// copy partition: 8,388,608 float4 = 2048 blocks x 4096 float4
#define CPY_A 512   // mega0
#define CPY_B 640   // nodeStats
#define CPY_C 512   // edge
#define CPY_D 384   // gemm1

typedef unsigned long long u64;
typedef unsigned int u32;

// ---------------- scratch ----------------
__device__ __align__(16) float g_Y[(size_t)PROWS * 512];
__device__ __align__(16) float g_node[(size_t)NROWS * 256];
__device__ __align__(16) float g_agg[(size_t)NROWS * 256];
__device__ __align__(16) float g_add[(size_t)NROWS * 256];
__device__ float g_AT[NROWS];
__device__ float g_AS[NROWS];
__device__ float g_AE[2];
__device__ float g_E[2][256];
__device__ float g_w0[NROWS];
__device__ float g_w1[NROWS];
__device__ int   g_hn[NROWS];
__device__ int   g_bhas[Bc];
__device__ int   g_rowcnt[NROWS];
__device__ int   g_rowoff[NROWS];
__device__ int   g_cand[(size_t)Bc * EDGECAP];
__device__ int   g_rows[NROWS];
__device__ int   g_nact;
__device__ int   g_clist[(size_t)Bc * 128 * 512];
__device__ int   g_ccnt[Bc * 128];

// ---------------- helpers ----------------
__device__ __forceinline__ u32 f2tf32(float f) {
    u32 r;
    asm("cvt.rna.tf32.f32 %0, %1;" : "=r"(r) : "f"(f));
    return r;
}
__device__ __forceinline__ void tf32split(float a, u32& hi, u32& lo) {
    hi = f2tf32(a);
    lo = f2tf32(a - __uint_as_float(hi));
}

#define MMA_TF32(C0, C1, C2, C3, A0, A1, A2, A3, B0, B1)                        \
    asm volatile(                                                                \
        "mma.sync.aligned.m16n8k8.row.col.f32.tf32.tf32.f32 "                    \
        "{%0,%1,%2,%3}, {%4,%5,%6,%7}, {%8,%9}, {%0,%1,%2,%3};"                  \
        : "+f"(C0), "+f"(C1), "+f"(C2), "+f"(C3)                                 \
        : "r"(A0), "r"(A1), "r"(A2), "r"(A3), "r"(B0), "r"(B1))

// ---------------- embedded copy block: 4096 float4 ----------------
__device__ __forceinline__ void copyBlk(float4* __restrict__ dst,
                                        const float4* __restrict__ src,
                                        int cblk, int tid)
{
    size_t base = ((size_t)cblk << 12) + tid;
#pragma unroll
    for (int i = 0; i < 16; i++) dst[base + (i << 8)] = src[base + (i << 8)];
}

#define AS_STRIDE 20
#define BS_STRIDE 136

// ============================================================================
// L1: gemm0 tf32-split (blocks 0..271) + build (272..303) + copyA
// ============================================================================
__global__ __launch_bounds__(256) void mega0Kernel(
    float* __restrict__ out, const float* __restrict__ emb,
    const float* __restrict__ W_trip,
    const int* __restrict__ asp_st, const int* __restrict__ asp_len,
    const int* __restrict__ opi_st, const int* __restrict__ opi_len,
    const float* __restrict__ edge_emb, const float* __restrict__ W_attn,
    const float* __restrict__ W_gat)
{
    cudaTriggerProgrammaticLaunchCompletion();
    int blk = blockIdx.x, tid = threadIdx.x;

    if (blk >= 304) {
        copyBlk((float4*)out, (const float4*)emb, blk - 304, tid);
        return;
    }

    if (blk < 272) {
        __shared__ __align__(16) u32 AsH[64 * AS_STRIDE];
        __shared__ __align__(16) u32 AsL[64 * AS_STRIDE];
        __shared__ __align__(16) u32 BsH[16 * BS_STRIDE];
        __shared__ __align__(16) u32 BsL[16 * BS_STRIDE];

        int bc = blk & 3, br = blk >> 2;
        int lane = tid & 31, wid = tid >> 5;
        int wm = wid & 3, wn = wid >> 2;

        int aRow = tid >> 2;
        int r = br * 64 + aRow;
        int b = r / TT, t = r - b * TT;
        const float* Ap = emb + ((size_t)(b * Lc + t)) * 256 + (tid & 3) * 4;
        int asw = aRow * AS_STRIDE + (tid & 3) * 4;

        int bkr = tid >> 4, bcg = (tid & 15) * 8;
        int j0 = bc * 128 + bcg;
        int half = (j0 >= 256);
        const float* Bp = W_trip + (size_t)(half * 256 + bkr) * 256 + (j0 - half * 256);
        int bsw = bkr * BS_STRIDE + bcg;

        float C[8][4];
#pragma unroll
        for (int j = 0; j < 8; j++)
#pragma unroll
            for (int i = 0; i < 4; i++) C[j][i] = 0.f;

        int g = lane >> 2, cc = lane & 3;

        float4 av = *(const float4*)Ap;
        float4 bv[2];
        bv[0] = *(const float4*)Bp;
        bv[1] = *(const float4*)(Bp + 4);

        for (int kc = 0; kc < 16; kc++) {
            {
                u32 h, l;
                tf32split(av.x, h, l); AsH[asw + 0] = h; AsL[asw + 0] = l;
                tf32split(av.y, h, l); AsH[asw + 1] = h; AsL[asw + 1] = l;
                tf32split(av.z, h, l); AsH[asw + 2] = h; AsL[asw + 2] = l;
                tf32split(av.w, h, l); AsH[asw + 3] = h; AsL[asw + 3] = l;
#pragma unroll
                for (int q = 0; q < 2; q++) {
                    tf32split(bv[q].x, h, l); BsH[bsw + q * 4 + 0] = h; BsL[bsw + q * 4 + 0] = l;
                    tf32split(bv[q].y, h, l); BsH[bsw + q * 4 + 1] = h; BsL[bsw + q * 4 + 1] = l;
                    tf32split(bv[q].z, h, l); BsH[bsw + q * 4 + 2] = h; BsL[bsw + q * 4 + 2] = l;
                    tf32split(bv[q].w, h, l); BsH[bsw + q * 4 + 3] = h; BsL[bsw + q * 4 + 3] = l;
                }
            }
            __syncthreads();
            bool more = (kc < 15);
            if (more) {
                av = *(const float4*)(Ap + (kc + 1) * 16);
                const float* bp = Bp + (size_t)((kc + 1) * 16) * 256;
                bv[0] = *(const float4*)bp;
                bv[1] = *(const float4*)(bp + 4);
            }
#pragma unroll
            for (int ks = 0; ks < 16; ks += 8) {
                int ra = (wm * 16 + g) * AS_STRIDE + ks + cc;
                int rb = (wm * 16 + g + 8) * AS_STRIDE + ks + cc;
                u32 ah0 = AsH[ra],     ah1 = AsH[rb];
                u32 ah2 = AsH[ra + 4], ah3 = AsH[rb + 4];
                u32 al0 = AsL[ra],     al1 = AsL[rb];
                u32 al2 = AsL[ra + 4], al3 = AsL[rb + 4];
                const u32* bh0p = &BsH[(ks + cc)     * BS_STRIDE + wn * 64 + g];
                const u32* bh1p = &BsH[(ks + cc + 4) * BS_STRIDE + wn * 64 + g];
                const u32* bl0p = &BsL[(ks + cc)     * BS_STRIDE + wn * 64 + g];
                const u32* bl1p = &BsL[(ks + cc + 4) * BS_STRIDE + wn * 64 + g];
#pragma unroll
                for (int j = 0; j < 8; j++) {
                    u32 bh0 = bh0p[j * 8], bh1 = bh1p[j * 8];
                    u32 bl0 = bl0p[j * 8], bl1 = bl1p[j * 8];
                    MMA_TF32(C[j][0], C[j][1], C[j][2], C[j][3],
                             ah0, ah1, ah2, ah3, bh0, bh1);
                    MMA_TF32(C[j][0], C[j][1], C[j][2], C[j][3],
                             ah0, ah1, ah2, ah3, bl0, bl1);
                    MMA_TF32(C[j][0], C[j][1], C[j][2], C[j][3],
                             al0, al1, al2, al3, bh0, bh1);
                }
            }
            __syncthreads();
        }

        int rr0 = br * 64 + wm * 16 + g;
        int rr1 = rr0 + 8;
#pragma unroll
        for (int j = 0; j < 8; j++) {
            int col = bc * 128 + wn * 64 + j * 8 + 2 * cc;
            float2 v0 = make_float2(C[j][0], C[j][1]);
            float2 v1 = make_float2(C[j][2], C[j][3]);
            *(float2*)&g_Y[(size_t)rr0 * 512 + col] = v0;
            *(float2*)&g_Y[(size_t)rr1 * 512 + col] = v1;
        }
        return;
    }

    // ---- build ----
    {
        int bb = blk - 272;
        int base = bb * Nc;
        __shared__ int ka[512], ko[512], cen[512];
        __shared__ int wsum[8];
        __shared__ int sc_cnt[128];
        for (int i = tid; i < 512; i += 256) {
            int st = asp_st[base + i], ln = asp_len[base + i];
            int so = opi_st[base + i], lo = opi_len[base + i];
            ka[i] = st | (ln << 16);
            ko[i] = so | (lo << 16);
            cen[i] = (st + so) >> 1;
        }
        if (tid < 128) sc_cnt[tid] = 0;
        __syncthreads();

        int t0 = 2 * tid, t1 = t0 + 1;
        int ka0 = ka[t0], ko0 = ko[t0], ce0 = cen[t0];
        int ka1 = ka[t1], ko1 = ko[t1], ce1 = cen[t1];
        int c0 = 0, c1 = 0, r0 = 0, r1 = 0;
        for (int s = 0; s < 512; s++) {
            int kas = ka[s], kos = ko[s], ces = cen[s];
            if (s != t0) c0 += (kas == ka0) + (kos == ko0);
            if (s != t1) c1 += (kas == ka1) + (kos == ko1);
            r0 += (s < t0 && ces == ce0);
            r1 += (s < t1 && ces == ce1);
        }
        int ps = c0 + c1;
        int lane = tid & 31, w = tid >> 5;
        int v = ps;
#pragma unroll
        for (int o = 1; o < 32; o <<= 1) {
            int n = __shfl_up_sync(0xffffffffu, v, o);
            if (lane >= o) v += n;
        }
        if (lane == 31) wsum[w] = v;
        __syncthreads();
        if (tid == 0) {
            int run = 0;
#pragma unroll
            for (int i = 0; i < 8; i++) { int x = wsum[i]; wsum[i] = run; run += x; }
        }
        __syncthreads();
        int off = v - ps + wsum[w];
        g_rowcnt[base + t0] = c0;
        g_rowcnt[base + t1] = c1;
        int p0 = bb * EDGECAP + off;
        int p1 = p0 + c0;
        g_rowoff[base + t0] = p0;
        g_rowoff[base + t1] = p1;
        for (int s = 0; s < 512; s++) {
            int kas = ka[s], kos = ko[s];
            if (s != t0) {
                if (kas == ka0) g_cand[p0++] = s;
                if (kos == ko0) g_cand[p0++] = s | (1 << 16);
            }
            if (s != t1) {
                if (kas == ka1) g_cand[p1++] = s;
                if (kos == ko1) g_cand[p1++] = s | (1 << 16);
            }
        }
        g_clist[((size_t)(bb * 128 + ce0) << 9) + r0] = t0;
        g_clist[((size_t)(bb * 128 + ce1) << 9) + r1] = t1;
        atomicAdd(&sc_cnt[ce0], 1);
        atomicAdd(&sc_cnt[ce1], 1);
        __syncthreads();
        if (tid < 128) g_ccnt[bb * 128 + tid] = sc_cnt[tid];

        if (bb == 0) {
            int h = tid;
#pragma unroll
            for (int e = 0; e < 2; e++) {
                float s = 0.f;
                for (int k = 0; k < 256; k++)
                    s += edge_emb[e * 256 + k] * W_gat[(size_t)(256 + k) * 256 + h];
                g_E[e][h] = s;
            }
            if (tid < 2) {
                float sa = 0.f;
                for (int k = 0; k < 256; k++) {
                    float vv = edge_emb[tid * 256 + k];
                    vv = (vv >= 0.f) ? vv : SLOPE * vv;
                    sa += vv * W_attn[512 + k];
                }
                g_AE[tid] = sa;
            }
            if (tid >= 4 && tid < 4 + Bc) g_bhas[tid - 4] = 0;
            if (tid == 2) g_nact = 0;
        }
    }
}

// ============================================================================
// L2: nodeStats (4 rows/block, float4) + copyB   [PDL secondary]
// ============================================================================
__global__ __launch_bounds__(256) void nodeStatsKernel(
    float* __restrict__ out, const float* __restrict__ emb,
    const int* __restrict__ asp_st, const int* __restrict__ asp_len,
    const int* __restrict__ opi_st, const int* __restrict__ opi_len,
    const int* __restrict__ sent, const float* __restrict__ W_trip,
    const float* __restrict__ b_trip, const float* __restrict__ W_attn)
{
    cudaTriggerProgrammaticLaunchCompletion();
    int blk = blockIdx.x, tid = threadIdx.x;
    if (blk >= 4096) {
        copyBlk((float4*)out, (const float4*)emb, CPY_A + (blk - 4096), tid);
        return;
    }
    cudaGridDependencySynchronize();   // wait for g_Y (mega0)

    int rib = tid >> 6;
    int c4 = tid & 63;
    int row = blk * 4 + rib;
    int b = row >> 9;
    const float4* Yb = (const float4*)(g_Y + (size_t)b * TT * 512);

    int ast = asp_st[row], aln = asp_len[row];
    int ost = opi_st[row], oln = opi_len[row];

    float4 asum = make_float4(0.f, 0.f, 0.f, 0.f);
#pragma unroll 4
    for (int k = 0; k <= aln; k++) {
        float4 v = Yb[(size_t)(ast + k) * 128 + c4];
        asum.x += v.x; asum.y += v.y; asum.z += v.z; asum.w += v.w;
    }
    float4 osum = make_float4(0.f, 0.f, 0.f, 0.f);
#pragma unroll 4
    for (int k = 0; k <= oln; k++) {
        float4 v = Yb[(size_t)(ost + k) * 128 + 64 + c4];
        osum.x += v.x; osum.y += v.y; osum.z += v.z; osum.w += v.w;
    }
    float ia = 1.f / (float)(aln + 1), io = 1.f / (float)(oln + 1);
    int sid = sent[row];
    float4 wt = ((const float4*)W_trip)[(size_t)(512 + sid) * 64 + c4];
    float4 bt = ((const float4*)b_trip)[c4];
    float4 v4;
    v4.x = asum.x * ia + osum.x * io + wt.x + bt.x;
    v4.y = asum.y * ia + osum.y * io + wt.y + bt.y;
    v4.z = asum.z * ia + osum.z * io + wt.z + bt.z;
    v4.w = asum.w * ia + osum.w * io + wt.w + bt.w;
    ((float4*)g_node)[((size_t)row << 6) + c4] = v4;

    float4 lv;
    lv.x = (v4.x >= 0.f) ? v4.x : SLOPE * v4.x;
    lv.y = (v4.y >= 0.f) ? v4.y : SLOPE * v4.y;
    lv.z = (v4.z >= 0.f) ? v4.z : SLOPE * v4.z;
    lv.w = (v4.w >= 0.f) ? v4.w : SLOPE * v4.w;
    float4 wat = ((const float4*)W_attn)[c4];
    float4 was = ((const float4*)W_attn)[64 + c4];
    float at = lv.x * wat.x + lv.y * wat.y + lv.z * wat.z + lv.w * wat.w;
    float as = lv.x * was.x + lv.y * was.y + lv.z * was.z + lv.w * was.w;
#pragma unroll
    for (int o = 16; o; o >>= 1) {
        at += __shfl_xor_sync(0xffffffffu, at, o);
        as += __shfl_xor_sync(0xffffffffu, as, o);
    }
    __shared__ float sAt[8], sAs[8];
    int w = tid >> 5;
    if ((tid & 31) == 0) { sAt[w] = at; sAs[w] = as; }
    __syncthreads();
    if (c4 == 0) {
        int w0 = rib * 2;
        g_AT[row] = sAt[w0] + sAt[w0 + 1];
        g_AS[row] = sAs[w0] + sAs[w0 + 1];
    }
}

// ============================================================================
// L3: edge (warp-per-row) + copyC   [PDL secondary]
// ============================================================================
__global__ __launch_bounds__(256) void edgeKernel(
    float* __restrict__ out, const float* __restrict__ emb,
    const float* __restrict__ b_attn)
{
    cudaTriggerProgrammaticLaunchCompletion();
    int blk = blockIdx.x, tid = threadIdx.x;
    if (blk >= 2048) {
        copyBlk((float4*)out, (const float4*)emb, CPY_A + CPY_B + (blk - 2048), tid);
        return;
    }
    cudaGridDependencySynchronize();   // wait for g_node/g_AT/g_AS (nodeStats; transitively build)

    __shared__ int   s_cand[8][WCAP];
    __shared__ float s_sc[8][WCAP];
    int warp = tid >> 5, lane = tid & 31;
    int row = blk * 8 + warp;
    int b = row >> 9, bs = b * Nc;

    int m1 = g_rowcnt[row];
    if (m1 == 0) {
        if (lane == 0) g_hn[row] = 0;
        return;
    }
    if (m1 > WCAP) m1 = WCAP;
    int off = g_rowoff[row];
    for (int e = lane; e < m1; e += 32) s_cand[warp][e] = g_cand[off + e];

    const float* rp = g_node + ((size_t)row << 8);
    float nT[8];
#pragma unroll
    for (int k = 0; k < 8; k++) nT[k] = rp[lane + 32 * k];
    __syncwarp();

    float atv = g_AT[row], bat = b_attn[0];
    int m2 = 0;
    for (int e = 0; e < m1; e++) {
        int cd = s_cand[warp][e];
        int s = cd & 0xffff;
        const float* ns = g_node + ((size_t)(bs + s) << 8);
        float d = 0.f;
#pragma unroll
        for (int k = 0; k < 8; k++) d += nT[k] * ns[lane + 32 * k];
#pragma unroll
        for (int o = 16; o; o >>= 1) d += __shfl_xor_sync(0xffffffffu, d, o);
        if (lane == 0) {
            if (d > 0.f) { s_sc[warp][e] = atv + g_AS[bs + s] + g_AE[cd >> 16] + bat; m2++; }
            else s_sc[warp][e] = NEGINF;
        }
    }
    m2 = __shfl_sync(0xffffffffu, m2, 0);
    float invden = 0.f;
    if (lane == 0) {
        g_hn[row] = (m2 > 0) ? 1 : 0;
        if (m2 > 0) {
            atomicOr(&g_bhas[b], 1);
            int p = atomicAdd(&g_nact, 1);
            g_rows[p] = row;
            float mx = NEGINF;
            for (int e = 0; e < m1; e++) mx = fmaxf(mx, s_sc[warp][e]);
            float den = 0.f, w0 = 0.f, w1 = 0.f;
            for (int e = 0; e < m1; e++) {
                float we = expf(s_sc[warp][e] - mx);
                s_sc[warp][e] = we;
                den += we;
                if ((s_cand[warp][e] >> 16) == 0) w0 += we; else w1 += we;
            }
            invden = 1.f / den;
            g_w0[row] = w0 / den;
            g_w1[row] = w1 / den;
        }
    }
    invden = __shfl_sync(0xffffffffu, invden, 0);
    __syncwarp();
    if (m2 > 0) {
        float acc[8];
#pragma unroll
        for (int k = 0; k < 8; k++) acc[k] = 0.f;
        for (int e = 0; e < m1; e++) {
            float we = s_sc[warp][e];
            if (we != 0.f) {
                int s = s_cand[warp][e] & 0xffff;
                const float* ns = g_node + ((size_t)(bs + s) << 8);
#pragma unroll
                for (int k = 0; k < 8; k++) acc[k] += we * ns[lane + 32 * k];
            }
        }
        float* ag = g_agg + ((size_t)row << 8);
#pragma unroll
        for (int k = 0; k < 8; k++) ag[lane + 32 * k] = acc[k] * invden;
    }
}

// ============================================================================
// L4: GEMM1 tf32 mma — 64x128 tiles + copyD   [PDL secondary]
// ============================================================================
__global__ __launch_bounds__(256) void gemm1Kernel(
    float* __restrict__ out, const float* __restrict__ emb,
    const float* __restrict__ W, const float* __restrict__ bias)
{
    cudaTriggerProgrammaticLaunchCompletion();
    int blk = blockIdx.x, tid = threadIdx.x;
    if (blk >= 512) {
        copyBlk((float4*)out, (const float4*)emb,
                CPY_A + CPY_B + CPY_C + (blk - 512), tid);
        return;
    }
    cudaGridDependencySynchronize();   // wait for g_agg/g_nact/g_rows (edge)

    int nact = g_nact;
    int bc = blk & 1, br = blk >> 1;
    if (br * 64 >= nact) return;
    int nrows = nact - br * 64;
    if (nrows > 64) nrows = 64;

    __shared__ __align__(16) u32 As[2][64 * AS_STRIDE];
    __shared__ __align__(16) u32 Bs[2][16 * BS_STRIDE];
    __shared__ float sB[128], sE0[128], sE1[128];
    __shared__ int rows[64];

    int lane = tid & 31, wid = tid >> 5;
    int wm = wid & 3, wn = wid >> 2;

    if (tid < 64) rows[tid] = g_rows[br * 64 + (tid < nrows ? tid : nrows - 1)];
    if (tid < 128) {
        int c = bc * 128 + tid;
        sB[tid]  = bias[c];
        sE0[tid] = g_E[0][c];
        sE1[tid] = g_E[1][c];
    }
    __syncthreads();

    const float* Ap = g_agg + ((size_t)rows[tid >> 2] << 8) + (tid & 3) * 4;
    int asw = (tid >> 2) * AS_STRIDE + (tid & 3) * 4;
    int bkr = tid >> 4, bcg = (tid & 15) * 8;
    const float* Bp = W + (size_t)bkr * 256 + bc * 128 + bcg;
    int bsw = bkr * BS_STRIDE + bcg;

    float C[8][4];
#pragma unroll
    for (int j = 0; j < 8; j++)
#pragma unroll
        for (int i = 0; i < 4; i++) C[j][i] = 0.f;

    int g = lane >> 2, cc = lane & 3;

    {
        float4 av = *(const float4*)Ap;
        As[0][asw + 0] = f2tf32(av.x); As[0][asw + 1] = f2tf32(av.y);
        As[0][asw + 2] = f2tf32(av.z); As[0][asw + 3] = f2tf32(av.w);
#pragma unroll
        for (int l = 0; l < 2; l++) {
            float4 bv = *(const float4*)(Bp + l * 4);
            Bs[0][bsw + l * 4 + 0] = f2tf32(bv.x); Bs[0][bsw + l * 4 + 1] = f2tf32(bv.y);
            Bs[0][bsw + l * 4 + 2] = f2tf32(bv.z); Bs[0][bsw + l * 4 + 3] = f2tf32(bv.w);
        }
    }
    __syncthreads();

    for (int kc = 0; kc < 16; kc++) {
        int cur = kc & 1;
        float4 av; float4 bv[2];
        bool more = (kc < 15);
        if (more) {
            av = *(const float4*)(Ap + (kc + 1) * 16);
            const float* bp = Bp + (size_t)((kc + 1) * 16) * 256;
#pragma unroll
            for (int l = 0; l < 2; l++) bv[l] = *(const float4*)(bp + l * 4);
        }
#pragma unroll
        for (int ks = 0; ks < 16; ks += 8) {
            u32 a0 = As[cur][(wm * 16 + g)     * AS_STRIDE + ks + cc];
            u32 a1 = As[cur][(wm * 16 + g + 8) * AS_STRIDE + ks + cc];
            u32 a2 = As[cur][(wm * 16 + g)     * AS_STRIDE + ks + cc + 4];
            u32 a3 = As[cur][(wm * 16 + g + 8) * AS_STRIDE + ks + cc + 4];
            const u32* b0p = &Bs[cur][(ks + cc)     * BS_STRIDE + wn * 64 + g];
            const u32* b1p = &Bs[cur][(ks + cc + 4) * BS_STRIDE + wn * 64 + g];
#pragma unroll
            for (int j = 0; j < 8; j++) {
                u32 b0 = b0p[j * 8];
                u32 b1 = b1p[j * 8];
                MMA_TF32(C[j][0], C[j][1], C[j][2], C[j][3], a0, a1, a2, a3, b0, b1);
            }
        }
        if (more) {
            int nxt = cur ^ 1;
            As[nxt][asw + 0] = f2tf32(av.x); As[nxt][asw + 1] = f2tf32(av.y);
            As[nxt][asw + 2] = f2tf32(av.z); As[nxt][asw + 3] = f2tf32(av.w);
#pragma unroll
            for (int l = 0; l < 2; l++) {
                Bs[nxt][bsw + l * 4 + 0] = f2tf32(bv[l].x);
                Bs[nxt][bsw + l * 4 + 1] = f2tf32(bv[l].y);
                Bs[nxt][bsw + l * 4 + 2] = f2tf32(bv[l].z);
                Bs[nxt][bsw + l * 4 + 3] = f2tf32(bv[l].w);
            }
            __syncthreads();
        }
    }

    int idx0 = wm * 16 + g, idx1 = idx0 + 8;
    bool ok0 = idx0 < nrows, ok1 = idx1 < nrows;
    int r0 = rows[idx0], r1 = rows[idx1];
    float w00 = g_w0[r0], w01 = g_w1[r0];
    float w10 = g_w0[r1], w11 = g_w1[r1];
#pragma unroll
    for (int j = 0; j < 8; j++) {
        int lc = wn * 64 + j * 8 + 2 * cc;
        int col = bc * 128 + lc;
        float bx = sB[lc],     e0x = sE0[lc],     e1x = sE1[lc];
        float by = sB[lc + 1], e0y = sE0[lc + 1], e1y = sE1[lc + 1];
        if (ok0) {
            float2 st;
            st.x = fmaxf(C[j][0] + bx + w00 * e0x + w01 * e1x, 0.f);
            st.y = fmaxf(C[j][1] + by + w00 * e0y + w01 * e1y, 0.f);
            *(float2*)&g_add[((size_t)r0 << 8) + col] = st;
        }
        if (ok1) {
            float2 st;
            st.x = fmaxf(C[j][2] + bx + w10 * e0x + w11 * e1x, 0.f);
            st.y = fmaxf(C[j][3] + by + w10 * e0y + w11 * e1y, 0.f);
            *(float2*)&g_add[((size_t)r1 << 8) + col] = st;
        }
    }
}

// ============================================================================
// L5: scatter via center lists   [PDL secondary]
// ============================================================================
__global__ __launch_bounds__(256) void scatterKernel(float* __restrict__ out)
{
    cudaTriggerProgrammaticLaunchCompletion();
    cudaGridDependencySynchronize();   // wait for g_add (gemm1; transitively all copies)
    int b = blockIdx.x >> 7;
    int c = blockIdx.x & 127;
    int h = threadIdx.x;
    if (!g_bhas[b]) return;
    int cnt = g_ccnt[b * 128 + c];
    if (cnt == 0) return;
    const int* list = g_clist + ((size_t)(b * 128 + c) << 9);
    float s = 0.f;
    for (int i = 0; i < cnt; i++) {
        int r = b * Nc + list[i];
        size_t o = ((size_t)r << 8) + h;
        s += g_hn[r] ? g_add[o] : g_node[o];
    }
    out[((size_t)b * Lc + c) * Hc + h] += s;
}

// ---------------- launch -----------------------------------------------------
extern "C" void kernel_launch(void* const* d_in, const int* in_sizes, int n_in,
                              void* d_out, int out_size)
{
    const float* emb     = (const float*)d_in[0];
    const float* W_trip  = (const float*)d_in[1];
    const float* b_trip  = (const float*)d_in[2];
    const float* edge_e  = (const float*)d_in[3];
    const float* W_attn  = (const float*)d_in[4];
    const float* b_attn  = (const float*)d_in[5];
    const float* W_gat   = (const float*)d_in[6];
    const float* b_gat   = (const float*)d_in[7];
    const int*   asp_st  = (const int*)d_in[8];
    const int*   asp_len = (const int*)d_in[9];
    const int*   opi_st  = (const int*)d_in[10];
    const int*   opi_len = (const int*)d_in[11];
    const int*   sent_id = (const int*)d_in[12];
    float* out = (float*)d_out;

    mega0Kernel<<<304 + CPY_A, 256>>>(out, emb, W_trip, asp_st, asp_len,
                                      opi_st, opi_len, edge_e, W_attn, W_gat);

    cudaLaunchAttribute attr[1];
    attr[0].id = cudaLaunchAttributeProgrammaticStreamSerialization;
    attr[0].val.programmaticStreamSerializationAllowed = 1;

    {
        cudaLaunchConfig_t cfg = {};
        cfg.gridDim = dim3(4096 + CPY_B);
        cfg.blockDim = dim3(256);
        cfg.stream = 0;
        cfg.attrs = attr;
        cfg.numAttrs = 1;
        cudaLaunchKernelEx(&cfg, nodeStatsKernel, out, emb, asp_st, asp_len,
                           opi_st, opi_len, sent_id, W_trip, b_trip, W_attn);
    }
    {
        cudaLaunchConfig_t cfg = {};
        cfg.gridDim = dim3(2048 + CPY_C);
        cfg.blockDim = dim3(256);
        cfg.stream = 0;
        cfg.attrs = attr;
        cfg.numAttrs = 1;
        cudaLaunchKernelEx(&cfg, edgeKernel, out, emb, b_attn);
    }
    {
        cudaLaunchConfig_t cfg = {};
        cfg.gridDim = dim3(512 + CPY_D);
        cfg.blockDim = dim3(256);
        cfg.stream = 0;
        cfg.attrs = attr;
        cfg.numAttrs = 1;
        cudaLaunchKernelEx(&cfg, gemm1Kernel, out, emb, W_gat, b_gat);
    }
    {
        cudaLaunchConfig_t cfg = {};
        cfg.gridDim = dim3(Bc * 128);
        cfg.blockDim = dim3(256);
        cfg.stream = 0;
        cfg.attrs = attr;
        cfg.numAttrs = 1;
        cudaLaunchKernelEx(&cfg, scatterKernel, out);
    }
}

// round 14
// speedup vs baseline: 1.3943x; 1.0308x over previous
#include <cuda_runtime.h>
#include <cstdint>

#define Bc 32
#define Lc 4096
#define Hc 256
#define Nc 512
#define NROWS (Bc * Nc)          // 16384
#define TT 136
#define PROWS (Bc * TT)          // 4352
#define SLOPE 0.2f
#define NEGINF (-3.4028234663852886e38f)
#define EDGECAP (Nc * (Nc - 1) * 2)
#define WCAP 256

// copy partition: 8,388,608 float4 = 2048 blocks x 4096 float4
#define CPY_A 512   // mega0 (copy-last: nothing precedes it)
#define CPY_B 640   // nodeStats (copy-FIRST)
#define CPY_C 512   // edge (copy-FIRST)
#define CPY_D 384   // gemm1 (copy-FIRST)

typedef unsigned long long u64;
typedef unsigned int u32;

// ---------------- scratch ----------------
__device__ __align__(16) float g_Y[(size_t)PROWS * 512];
__device__ __align__(16) float g_node[(size_t)NROWS * 256];
__device__ __align__(16) float g_agg[(size_t)NROWS * 256];
__device__ __align__(16) float g_add[(size_t)NROWS * 256];
__device__ float g_AT[NROWS];
__device__ float g_AS[NROWS];
__device__ float g_AE[2];
__device__ float g_E[2][256];
__device__ float g_w0[NROWS];
__device__ float g_w1[NROWS];
__device__ int   g_hn[NROWS];
__device__ int   g_bhas[Bc];
__device__ int   g_rowcnt[NROWS];
__device__ int   g_rowoff[NROWS];
__device__ int   g_cand[(size_t)Bc * EDGECAP];
__device__ int   g_rows[NROWS];
__device__ int   g_nact;
__device__ int   g_clist[(size_t)Bc * 128 * 512];
__device__ int   g_ccnt[Bc * 128];

// ---------------- helpers ----------------
__device__ __forceinline__ u32 f2tf32(float f) {
    u32 r;
    asm("cvt.rna.tf32.f32 %0, %1;" : "=r"(r) : "f"(f));
    return r;
}
__device__ __forceinline__ void tf32split(float a, u32& hi, u32& lo) {
    hi = f2tf32(a);
    lo = f2tf32(a - __uint_as_float(hi));
}

#define MMA_TF32(C0, C1, C2, C3, A0, A1, A2, A3, B0, B1)                        \
    asm volatile(                                                                \
        "mma.sync.aligned.m16n8k8.row.col.f32.tf32.tf32.f32 "                    \
        "{%0,%1,%2,%3}, {%4,%5,%6,%7}, {%8,%9}, {%0,%1,%2,%3};"                  \
        : "+f"(C0), "+f"(C1), "+f"(C2), "+f"(C3)                                 \
        : "r"(A0), "r"(A1), "r"(A2), "r"(A3), "r"(B0), "r"(B1))

// ---------------- embedded copy block: 4096 float4 ----------------
__device__ __forceinline__ void copyBlk(float4* __restrict__ dst,
                                        const float4* __restrict__ src,
                                        int cblk, int tid)
{
    size_t base = ((size_t)cblk << 12) + tid;
#pragma unroll
    for (int i = 0; i < 16; i++) dst[base + (i << 8)] = src[base + (i << 8)];
}

#define AS_STRIDE 20
#define BS_STRIDE 136

// ============================================================================
// L1: gemm0 tf32-split (blocks 0..271) + build (272..303) + copyA (last)
// ============================================================================
__global__ __launch_bounds__(256) void mega0Kernel(
    float* __restrict__ out, const float* __restrict__ emb,
    const float* __restrict__ W_trip,
    const int* __restrict__ asp_st, const int* __restrict__ asp_len,
    const int* __restrict__ opi_st, const int* __restrict__ opi_len,
    const float* __restrict__ edge_emb, const float* __restrict__ W_attn,
    const float* __restrict__ W_gat)
{
    cudaTriggerProgrammaticLaunchCompletion();
    int blk = blockIdx.x, tid = threadIdx.x;

    if (blk >= 304) {
        copyBlk((float4*)out, (const float4*)emb, blk - 304, tid);
        return;
    }

    if (blk < 272) {
        __shared__ __align__(16) u32 AsH[64 * AS_STRIDE];
        __shared__ __align__(16) u32 AsL[64 * AS_STRIDE];
        __shared__ __align__(16) u32 BsH[16 * BS_STRIDE];
        __shared__ __align__(16) u32 BsL[16 * BS_STRIDE];

        int bc = blk & 3, br = blk >> 2;
        int lane = tid & 31, wid = tid >> 5;
        int wm = wid & 3, wn = wid >> 2;

        int aRow = tid >> 2;
        int r = br * 64 + aRow;
        int b = r / TT, t = r - b * TT;
        const float* Ap = emb + ((size_t)(b * Lc + t)) * 256 + (tid & 3) * 4;
        int asw = aRow * AS_STRIDE + (tid & 3) * 4;

        int bkr = tid >> 4, bcg = (tid & 15) * 8;
        int j0 = bc * 128 + bcg;
        int half = (j0 >= 256);
        const float* Bp = W_trip + (size_t)(half * 256 + bkr) * 256 + (j0 - half * 256);
        int bsw = bkr * BS_STRIDE + bcg;

        float C[8][4];
#pragma unroll
        for (int j = 0; j < 8; j++)
#pragma unroll
            for (int i = 0; i < 4; i++) C[j][i] = 0.f;

        int g = lane >> 2, cc = lane & 3;

        float4 av = *(const float4*)Ap;
        float4 bv[2];
        bv[0] = *(const float4*)Bp;
        bv[1] = *(const float4*)(Bp + 4);

        for (int kc = 0; kc < 16; kc++) {
            {
                u32 h, l;
                tf32split(av.x, h, l); AsH[asw + 0] = h; AsL[asw + 0] = l;
                tf32split(av.y, h, l); AsH[asw + 1] = h; AsL[asw + 1] = l;
                tf32split(av.z, h, l); AsH[asw + 2] = h; AsL[asw + 2] = l;
                tf32split(av.w, h, l); AsH[asw + 3] = h; AsL[asw + 3] = l;
#pragma unroll
                for (int q = 0; q < 2; q++) {
                    tf32split(bv[q].x, h, l); BsH[bsw + q * 4 + 0] = h; BsL[bsw + q * 4 + 0] = l;
                    tf32split(bv[q].y, h, l); BsH[bsw + q * 4 + 1] = h; BsL[bsw + q * 4 + 1] = l;
                    tf32split(bv[q].z, h, l); BsH[bsw + q * 4 + 2] = h; BsL[bsw + q * 4 + 2] = l;
                    tf32split(bv[q].w, h, l); BsH[bsw + q * 4 + 3] = h; BsL[bsw + q * 4 + 3] = l;
                }
            }
            __syncthreads();
            bool more = (kc < 15);
            if (more) {
                av = *(const float4*)(Ap + (kc + 1) * 16);
                const float* bp = Bp + (size_t)((kc + 1) * 16) * 256;
                bv[0] = *(const float4*)bp;
                bv[1] = *(const float4*)(bp + 4);
            }
#pragma unroll
            for (int ks = 0; ks < 16; ks += 8) {
                int ra = (wm * 16 + g) * AS_STRIDE + ks + cc;
                int rb = (wm * 16 + g + 8) * AS_STRIDE + ks + cc;
                u32 ah0 = AsH[ra],     ah1 = AsH[rb];
                u32 ah2 = AsH[ra + 4], ah3 = AsH[rb + 4];
                u32 al0 = AsL[ra],     al1 = AsL[rb];
                u32 al2 = AsL[ra + 4], al3 = AsL[rb + 4];
                const u32* bh0p = &BsH[(ks + cc)     * BS_STRIDE + wn * 64 + g];
                const u32* bh1p = &BsH[(ks + cc + 4) * BS_STRIDE + wn * 64 + g];
                const u32* bl0p = &BsL[(ks + cc)     * BS_STRIDE + wn * 64 + g];
                const u32* bl1p = &BsL[(ks + cc + 4) * BS_STRIDE + wn * 64 + g];
#pragma unroll
                for (int j = 0; j < 8; j++) {
                    u32 bh0 = bh0p[j * 8], bh1 = bh1p[j * 8];
                    u32 bl0 = bl0p[j * 8], bl1 = bl1p[j * 8];
                    MMA_TF32(C[j][0], C[j][1], C[j][2], C[j][3],
                             ah0, ah1, ah2, ah3, bh0, bh1);
                    MMA_TF32(C[j][0], C[j][1], C[j][2], C[j][3],
                             ah0, ah1, ah2, ah3, bl0, bl1);
                    MMA_TF32(C[j][0], C[j][1], C[j][2], C[j][3],
                             al0, al1, al2, al3, bh0, bh1);
                }
            }
            __syncthreads();
        }

        int rr0 = br * 64 + wm * 16 + g;
        int rr1 = rr0 + 8;
#pragma unroll
        for (int j = 0; j < 8; j++) {
            int col = bc * 128 + wn * 64 + j * 8 + 2 * cc;
            float2 v0 = make_float2(C[j][0], C[j][1]);
            float2 v1 = make_float2(C[j][2], C[j][3]);
            *(float2*)&g_Y[(size_t)rr0 * 512 + col] = v0;
            *(float2*)&g_Y[(size_t)rr1 * 512 + col] = v1;
        }
        return;
    }

    // ---- build ----
    {
        int bb = blk - 272;
        int base = bb * Nc;
        __shared__ int ka[512], ko[512], cen[512];
        __shared__ int wsum[8];
        __shared__ int sc_cnt[128];
        for (int i = tid; i < 512; i += 256) {
            int st = asp_st[base + i], ln = asp_len[base + i];
            int so = opi_st[base + i], lo = opi_len[base + i];
            ka[i] = st | (ln << 16);
            ko[i] = so | (lo << 16);
            cen[i] = (st + so) >> 1;
        }
        if (tid < 128) sc_cnt[tid] = 0;
        __syncthreads();

        int t0 = 2 * tid, t1 = t0 + 1;
        int ka0 = ka[t0], ko0 = ko[t0], ce0 = cen[t0];
        int ka1 = ka[t1], ko1 = ko[t1], ce1 = cen[t1];
        int c0 = 0, c1 = 0, r0 = 0, r1 = 0;
        for (int s = 0; s < 512; s++) {
            int kas = ka[s], kos = ko[s], ces = cen[s];
            if (s != t0) c0 += (kas == ka0) + (kos == ko0);
            if (s != t1) c1 += (kas == ka1) + (kos == ko1);
            r0 += (s < t0 && ces == ce0);
            r1 += (s < t1 && ces == ce1);
        }
        int ps = c0 + c1;
        int lane = tid & 31, w = tid >> 5;
        int v = ps;
#pragma unroll
        for (int o = 1; o < 32; o <<= 1) {
            int n = __shfl_up_sync(0xffffffffu, v, o);
            if (lane >= o) v += n;
        }
        if (lane == 31) wsum[w] = v;
        __syncthreads();
        if (tid == 0) {
            int run = 0;
#pragma unroll
            for (int i = 0; i < 8; i++) { int x = wsum[i]; wsum[i] = run; run += x; }
        }
        __syncthreads();
        int off = v - ps + wsum[w];
        g_rowcnt[base + t0] = c0;
        g_rowcnt[base + t1] = c1;
        int p0 = bb * EDGECAP + off;
        int p1 = p0 + c0;
        g_rowoff[base + t0] = p0;
        g_rowoff[base + t1] = p1;
        for (int s = 0; s < 512; s++) {
            int kas = ka[s], kos = ko[s];
            if (s != t0) {
                if (kas == ka0) g_cand[p0++] = s;
                if (kos == ko0) g_cand[p0++] = s | (1 << 16);
            }
            if (s != t1) {
                if (kas == ka1) g_cand[p1++] = s;
                if (kos == ko1) g_cand[p1++] = s | (1 << 16);
            }
        }
        g_clist[((size_t)(bb * 128 + ce0) << 9) + r0] = t0;
        g_clist[((size_t)(bb * 128 + ce1) << 9) + r1] = t1;
        atomicAdd(&sc_cnt[ce0], 1);
        atomicAdd(&sc_cnt[ce1], 1);
        __syncthreads();
        if (tid < 128) g_ccnt[bb * 128 + tid] = sc_cnt[tid];

        if (bb == 0) {
            int h = tid;
#pragma unroll
            for (int e = 0; e < 2; e++) {
                float s = 0.f;
                for (int k = 0; k < 256; k++)
                    s += edge_emb[e * 256 + k] * W_gat[(size_t)(256 + k) * 256 + h];
                g_E[e][h] = s;
            }
            if (tid < 2) {
                float sa = 0.f;
                for (int k = 0; k < 256; k++) {
                    float vv = edge_emb[tid * 256 + k];
                    vv = (vv >= 0.f) ? vv : SLOPE * vv;
                    sa += vv * W_attn[512 + k];
                }
                g_AE[tid] = sa;
            }
            if (tid >= 4 && tid < 4 + Bc) g_bhas[tid - 4] = 0;
            if (tid == 2) g_nact = 0;
        }
    }
}

// ============================================================================
// L2: copyB (blocks 0..639, FIRST) + nodeStats (640..4735)   [PDL secondary]
// ============================================================================
__global__ __launch_bounds__(256) void nodeStatsKernel(
    float* __restrict__ out, const float* __restrict__ emb,
    const int* __restrict__ asp_st, const int* __restrict__ asp_len,
    const int* __restrict__ opi_st, const int* __restrict__ opi_len,
    const int* __restrict__ sent, const float* __restrict__ W_trip,
    const float* __restrict__ b_trip, const float* __restrict__ W_attn)
{
    cudaTriggerProgrammaticLaunchCompletion();
    int blk = blockIdx.x, tid = threadIdx.x;
    if (blk < CPY_B) {     // copy blocks run immediately — overlap mega0 tail
        copyBlk((float4*)out, (const float4*)emb, CPY_A + blk, tid);
        return;
    }
    cudaGridDependencySynchronize();   // wait for g_Y (mega0)

    int cblk = blk - CPY_B;
    int rib = tid >> 6;
    int c4 = tid & 63;
    int row = cblk * 4 + rib;
    int b = row >> 9;
    const float4* Yb = (const float4*)(g_Y + (size_t)b * TT * 512);

    int ast = asp_st[row], aln = asp_len[row];
    int ost = opi_st[row], oln = opi_len[row];

    float4 asum = make_float4(0.f, 0.f, 0.f, 0.f);
#pragma unroll 4
    for (int k = 0; k <= aln; k++) {
        float4 v = Yb[(size_t)(ast + k) * 128 + c4];
        asum.x += v.x; asum.y += v.y; asum.z += v.z; asum.w += v.w;
    }
    float4 osum = make_float4(0.f, 0.f, 0.f, 0.f);
#pragma unroll 4
    for (int k = 0; k <= oln; k++) {
        float4 v = Yb[(size_t)(ost + k) * 128 + 64 + c4];
        osum.x += v.x; osum.y += v.y; osum.z += v.z; osum.w += v.w;
    }
    float ia = 1.f / (float)(aln + 1), io = 1.f / (float)(oln + 1);
    int sid = sent[row];
    float4 wt = ((const float4*)W_trip)[(size_t)(512 + sid) * 64 + c4];
    float4 bt = ((const float4*)b_trip)[c4];
    float4 v4;
    v4.x = asum.x * ia + osum.x * io + wt.x + bt.x;
    v4.y = asum.y * ia + osum.y * io + wt.y + bt.y;
    v4.z = asum.z * ia + osum.z * io + wt.z + bt.z;
    v4.w = asum.w * ia + osum.w * io + wt.w + bt.w;
    ((float4*)g_node)[((size_t)row << 6) + c4] = v4;

    float4 lv;
    lv.x = (v4.x >= 0.f) ? v4.x : SLOPE * v4.x;
    lv.y = (v4.y >= 0.f) ? v4.y : SLOPE * v4.y;
    lv.z = (v4.z >= 0.f) ? v4.z : SLOPE * v4.z;
    lv.w = (v4.w >= 0.f) ? v4.w : SLOPE * v4.w;
    float4 wat = ((const float4*)W_attn)[c4];
    float4 was = ((const float4*)W_attn)[64 + c4];
    float at = lv.x * wat.x + lv.y * wat.y + lv.z * wat.z + lv.w * wat.w;
    float as = lv.x * was.x + lv.y * was.y + lv.z * was.z + lv.w * was.w;
#pragma unroll
    for (int o = 16; o; o >>= 1) {
        at += __shfl_xor_sync(0xffffffffu, at, o);
        as += __shfl_xor_sync(0xffffffffu, as, o);
    }
    __shared__ float sAt[8], sAs[8];
    int w = tid >> 5;
    if ((tid & 31) == 0) { sAt[w] = at; sAs[w] = as; }
    __syncthreads();
    if (c4 == 0) {
        int w0 = rib * 2;
        g_AT[row] = sAt[w0] + sAt[w0 + 1];
        g_AS[row] = sAs[w0] + sAs[w0 + 1];
    }
}

// ============================================================================
// L3: copyC (blocks 0..511, FIRST) + edge (512..2559)   [PDL secondary]
// ============================================================================
__global__ __launch_bounds__(256) void edgeKernel(
    float* __restrict__ out, const float* __restrict__ emb,
    const float* __restrict__ b_attn)
{
    cudaTriggerProgrammaticLaunchCompletion();
    int blk = blockIdx.x, tid = threadIdx.x;
    if (blk < CPY_C) {
        copyBlk((float4*)out, (const float4*)emb, CPY_A + CPY_B + blk, tid);
        return;
    }
    cudaGridDependencySynchronize();   // wait for g_node/g_AT/g_AS

    int cblk = blk - CPY_C;
    __shared__ int   s_cand[8][WCAP];
    __shared__ float s_sc[8][WCAP];
    int warp = tid >> 5, lane = tid & 31;
    int row = cblk * 8 + warp;
    int b = row >> 9, bs = b * Nc;

    int m1 = g_rowcnt[row];
    if (m1 == 0) {
        if (lane == 0) g_hn[row] = 0;
        return;
    }
    if (m1 > WCAP) m1 = WCAP;
    int off = g_rowoff[row];
    for (int e = lane; e < m1; e += 32) s_cand[warp][e] = g_cand[off + e];

    const float* rp = g_node + ((size_t)row << 8);
    float nT[8];
#pragma unroll
    for (int k = 0; k < 8; k++) nT[k] = rp[lane + 32 * k];
    __syncwarp();

    float atv = g_AT[row], bat = b_attn[0];
    int m2 = 0;
    for (int e = 0; e < m1; e++) {
        int cd = s_cand[warp][e];
        int s = cd & 0xffff;
        const float* ns = g_node + ((size_t)(bs + s) << 8);
        float d = 0.f;
#pragma unroll
        for (int k = 0; k < 8; k++) d += nT[k] * ns[lane + 32 * k];
#pragma unroll
        for (int o = 16; o; o >>= 1) d += __shfl_xor_sync(0xffffffffu, d, o);
        if (lane == 0) {
            if (d > 0.f) { s_sc[warp][e] = atv + g_AS[bs + s] + g_AE[cd >> 16] + bat; m2++; }
            else s_sc[warp][e] = NEGINF;
        }
    }
    m2 = __shfl_sync(0xffffffffu, m2, 0);
    float invden = 0.f;
    if (lane == 0) {
        g_hn[row] = (m2 > 0) ? 1 : 0;
        if (m2 > 0) {
            atomicOr(&g_bhas[b], 1);
            int p = atomicAdd(&g_nact, 1);
            g_rows[p] = row;
            float mx = NEGINF;
            for (int e = 0; e < m1; e++) mx = fmaxf(mx, s_sc[warp][e]);
            float den = 0.f, w0 = 0.f, w1 = 0.f;
            for (int e = 0; e < m1; e++) {
                float we = expf(s_sc[warp][e] - mx);
                s_sc[warp][e] = we;
                den += we;
                if ((s_cand[warp][e] >> 16) == 0) w0 += we; else w1 += we;
            }
            invden = 1.f / den;
            g_w0[row] = w0 / den;
            g_w1[row] = w1 / den;
        }
    }
    invden = __shfl_sync(0xffffffffu, invden, 0);
    __syncwarp();
    if (m2 > 0) {
        float acc[8];
#pragma unroll
        for (int k = 0; k < 8; k++) acc[k] = 0.f;
        for (int e = 0; e < m1; e++) {
            float we = s_sc[warp][e];
            if (we != 0.f) {
                int s = s_cand[warp][e] & 0xffff;
                const float* ns = g_node + ((size_t)(bs + s) << 8);
#pragma unroll
                for (int k = 0; k < 8; k++) acc[k] += we * ns[lane + 32 * k];
            }
        }
        float* ag = g_agg + ((size_t)row << 8);
#pragma unroll
        for (int k = 0; k < 8; k++) ag[lane + 32 * k] = acc[k] * invden;
    }
}

// ============================================================================
// L4: copyD (blocks 0..383, FIRST) + GEMM1 tf32 (384..895)   [PDL secondary]
// ============================================================================
__global__ __launch_bounds__(256) void gemm1Kernel(
    float* __restrict__ out, const float* __restrict__ emb,
    const float* __restrict__ W, const float* __restrict__ bias)
{
    cudaTriggerProgrammaticLaunchCompletion();
    int blk = blockIdx.x, tid = threadIdx.x;
    if (blk < CPY_D) {
        copyBlk((float4*)out, (const float4*)emb, CPY_A + CPY_B + CPY_C + blk, tid);
        return;
    }
    cudaGridDependencySynchronize();   // wait for g_agg/g_nact/g_rows

    int tblk = blk - CPY_D;
    int nact = g_nact;
    int bc = tblk & 1, br = tblk >> 1;
    if (br * 64 >= nact) return;
    int nrows = nact - br * 64;
    if (nrows > 64) nrows = 64;

    __shared__ __align__(16) u32 As[2][64 * AS_STRIDE];
    __shared__ __align__(16) u32 Bs[2][16 * BS_STRIDE];
    __shared__ float sB[128], sE0[128], sE1[128];
    __shared__ int rows[64];

    int lane = tid & 31, wid = tid >> 5;
    int wm = wid & 3, wn = wid >> 2;

    if (tid < 64) rows[tid] = g_rows[br * 64 + (tid < nrows ? tid : nrows - 1)];
    if (tid < 128) {
        int c = bc * 128 + tid;
        sB[tid]  = bias[c];
        sE0[tid] = g_E[0][c];
        sE1[tid] = g_E[1][c];
    }
    __syncthreads();

    const float* Ap = g_agg + ((size_t)rows[tid >> 2] << 8) + (tid & 3) * 4;
    int asw = (tid >> 2) * AS_STRIDE + (tid & 3) * 4;
    int bkr = tid >> 4, bcg = (tid & 15) * 8;
    const float* Bp = W + (size_t)bkr * 256 + bc * 128 + bcg;
    int bsw = bkr * BS_STRIDE + bcg;

    float C[8][4];
#pragma unroll
    for (int j = 0; j < 8; j++)
#pragma unroll
        for (int i = 0; i < 4; i++) C[j][i] = 0.f;

    int g = lane >> 2, cc = lane & 3;

    {
        float4 av = *(const float4*)Ap;
        As[0][asw + 0] = f2tf32(av.x); As[0][asw + 1] = f2tf32(av.y);
        As[0][asw + 2] = f2tf32(av.z); As[0][asw + 3] = f2tf32(av.w);
#pragma unroll
        for (int l = 0; l < 2; l++) {
            float4 bv = *(const float4*)(Bp + l * 4);
            Bs[0][bsw + l * 4 + 0] = f2tf32(bv.x); Bs[0][bsw + l * 4 + 1] = f2tf32(bv.y);
            Bs[0][bsw + l * 4 + 2] = f2tf32(bv.z); Bs[0][bsw + l * 4 + 3] = f2tf32(bv.w);
        }
    }
    __syncthreads();

    for (int kc = 0; kc < 16; kc++) {
        int cur = kc & 1;
        float4 av; float4 bv[2];
        bool more = (kc < 15);
        if (more) {
            av = *(const float4*)(Ap + (kc + 1) * 16);
            const float* bp = Bp + (size_t)((kc + 1) * 16) * 256;
#pragma unroll
            for (int l = 0; l < 2; l++) bv[l] = *(const float4*)(bp + l * 4);
        }
#pragma unroll
        for (int ks = 0; ks < 16; ks += 8) {
            u32 a0 = As[cur][(wm * 16 + g)     * AS_STRIDE + ks + cc];
            u32 a1 = As[cur][(wm * 16 + g + 8) * AS_STRIDE + ks + cc];
            u32 a2 = As[cur][(wm * 16 + g)     * AS_STRIDE + ks + cc + 4];
            u32 a3 = As[cur][(wm * 16 + g + 8) * AS_STRIDE + ks + cc + 4];
            const u32* b0p = &Bs[cur][(ks + cc)     * BS_STRIDE + wn * 64 + g];
            const u32* b1p = &Bs[cur][(ks + cc + 4) * BS_STRIDE + wn * 64 + g];
#pragma unroll
            for (int j = 0; j < 8; j++) {
                u32 b0 = b0p[j * 8];
                u32 b1 = b1p[j * 8];
                MMA_TF32(C[j][0], C[j][1], C[j][2], C[j][3], a0, a1, a2, a3, b0, b1);
            }
        }
        if (more) {
            int nxt = cur ^ 1;
            As[nxt][asw + 0] = f2tf32(av.x); As[nxt][asw + 1] = f2tf32(av.y);
            As[nxt][asw + 2] = f2tf32(av.z); As[nxt][asw + 3] = f2tf32(av.w);
#pragma unroll
            for (int l = 0; l < 2; l++) {
                Bs[nxt][bsw + l * 4 + 0] = f2tf32(bv[l].x);
                Bs[nxt][bsw + l * 4 + 1] = f2tf32(bv[l].y);
                Bs[nxt][bsw + l * 4 + 2] = f2tf32(bv[l].z);
                Bs[nxt][bsw + l * 4 + 3] = f2tf32(bv[l].w);
            }
            __syncthreads();
        }
    }

    int idx0 = wm * 16 + g, idx1 = idx0 + 8;
    bool ok0 = idx0 < nrows, ok1 = idx1 < nrows;
    int r0 = rows[idx0], r1 = rows[idx1];
    float w00 = g_w0[r0], w01 = g_w1[r0];
    float w10 = g_w0[r1], w11 = g_w1[r1];
#pragma unroll
    for (int j = 0; j < 8; j++) {
        int lc = wn * 64 + j * 8 + 2 * cc;
        int col = bc * 128 + lc;
        float bx = sB[lc],     e0x = sE0[lc],     e1x = sE1[lc];
        float by = sB[lc + 1], e0y = sE0[lc + 1], e1y = sE1[lc + 1];
        if (ok0) {
            float2 st;
            st.x = fmaxf(C[j][0] + bx + w00 * e0x + w01 * e1x, 0.f);
            st.y = fmaxf(C[j][1] + by + w00 * e0y + w01 * e1y, 0.f);
            *(float2*)&g_add[((size_t)r0 << 8) + col] = st;
        }
        if (ok1) {
            float2 st;
            st.x = fmaxf(C[j][2] + bx + w10 * e0x + w11 * e1x, 0.f);
            st.y = fmaxf(C[j][3] + by + w10 * e0y + w11 * e1y, 0.f);
            *(float2*)&g_add[((size_t)r1 << 8) + col] = st;
        }
    }
}

// ============================================================================
// L5: scatter via center lists   [PDL secondary]
// ============================================================================
__global__ __launch_bounds__(256) void scatterKernel(float* __restrict__ out)
{
    cudaTriggerProgrammaticLaunchCompletion();
    cudaGridDependencySynchronize();   // wait for g_add (and transitively all copies)
    int b = blockIdx.x >> 7;
    int c = blockIdx.x & 127;
    int h = threadIdx.x;
    if (!g_bhas[b]) return;
    int cnt = g_ccnt[b * 128 + c];
    if (cnt == 0) return;
    const int* list = g_clist + ((size_t)(b * 128 + c) << 9);
    float s = 0.f;
    for (int i = 0; i < cnt; i++) {
        int r = b * Nc + list[i];
        size_t o = ((size_t)r << 8) + h;
        s += g_hn[r] ? g_add[o] : g_node[o];
    }
    out[((size_t)b * Lc + c) * Hc + h] += s;
}

// ---------------- launch -----------------------------------------------------
extern "C" void kernel_launch(void* const* d_in, const int* in_sizes, int n_in,
                              void* d_out, int out_size)
{
    const float* emb     = (const float*)d_in[0];
    const float* W_trip  = (const float*)d_in[1];
    const float* b_trip  = (const float*)d_in[2];
    const float* edge_e  = (const float*)d_in[3];
    const float* W_attn  = (const float*)d_in[4];
    const float* b_attn  = (const float*)d_in[5];
    const float* W_gat   = (const float*)d_in[6];
    const float* b_gat   = (const float*)d_in[7];
    const int*   asp_st  = (const int*)d_in[8];
    const int*   asp_len = (const int*)d_in[9];
    const int*   opi_st  = (const int*)d_in[10];
    const int*   opi_len = (const int*)d_in[11];
    const int*   sent_id = (const int*)d_in[12];
    float* out = (float*)d_out;

    mega0Kernel<<<304 + CPY_A, 256>>>(out, emb, W_trip, asp_st, asp_len,
                                      opi_st, opi_len, edge_e, W_attn, W_gat);

    cudaLaunchAttribute attr[1];
    attr[0].id = cudaLaunchAttributeProgrammaticStreamSerialization;
    attr[0].val.programmaticStreamSerializationAllowed = 1;

    {
        cudaLaunchConfig_t cfg = {};
        cfg.gridDim = dim3(4096 + CPY_B);
        cfg.blockDim = dim3(256);
        cfg.stream = 0;
        cfg.attrs = attr;
        cfg.numAttrs = 1;
        cudaLaunchKernelEx(&cfg, nodeStatsKernel, out, emb, asp_st, asp_len,
                           opi_st, opi_len, sent_id, W_trip, b_trip, W_attn);
    }
    {
        cudaLaunchConfig_t cfg = {};
        cfg.gridDim = dim3(2048 + CPY_C);
        cfg.blockDim = dim3(256);
        cfg.stream = 0;
        cfg.attrs = attr;
        cfg.numAttrs = 1;
        cudaLaunchKernelEx(&cfg, edgeKernel, out, emb, b_attn);
    }
    {
        cudaLaunchConfig_t cfg = {};
        cfg.gridDim = dim3(512 + CPY_D);
        cfg.blockDim = dim3(256);
        cfg.stream = 0;
        cfg.attrs = attr;
        cfg.numAttrs = 1;
        cudaLaunchKernelEx(&cfg, gemm1Kernel, out, emb, W_gat, b_gat);
    }
    {
        cudaLaunchConfig_t cfg = {};
        cfg.gridDim = dim3(Bc * 128);
        cfg.blockDim = dim3(256);
        cfg.stream = 0;
        cfg.attrs = attr;
        cfg.numAttrs = 1;
        cudaLaunchKernelEx(&cfg, scatterKernel, out);
    }
}